// round 1
// baseline (speedup 1.0000x reference)
#include <cuda_runtime.h>
#include <cuda_bf16.h>
#include <math.h>

// ---------------------------------------------------------------------------
// Problem constants
// ---------------------------------------------------------------------------
#define BATCH 64
#define DMODEL 1024
#define NHEAD 16
#define HDIM 64
#define TMAX 2048
#define DFF 4096
#define LN_EPS 1e-5f

// ---------------------------------------------------------------------------
// Scratch (device globals; no allocation allowed)
// ---------------------------------------------------------------------------
__device__ float g_qkv[BATCH * 3 * DMODEL];   // [64, 3072]
__device__ float g_o  [BATCH * DMODEL];       // attention output
__device__ float g_x1 [BATCH * DMODEL];       // residual + out proj
__device__ float g_ln1[BATCH * DMODEL];       // after LN1
__device__ float g_h  [BATCH * DFF];          // MLP hidden
__device__ float g_x2 [BATCH * DMODEL];       // residual + mlp2

// ---------------------------------------------------------------------------
// GEMM: C[64,N] = A[64,K] @ B[K,N] (+bias) (+relu | +residual)
// BM=64, BN=32, BK=32, 128 threads, 4x4 micro-tile per thread.
// OP: 0 = bias, 1 = bias+relu, 2 = bias+residual
// ---------------------------------------------------------------------------
template<int OP>
__global__ void __launch_bounds__(128)
gemm64(const float* __restrict__ A, const float* __restrict__ B,
       const float* __restrict__ bias, const float* __restrict__ res,
       float* __restrict__ C, int N, int K)
{
    __shared__ float As[32][68];   // [k][m], padded
    __shared__ float Bs[32][32];   // [k][n]

    const int tid = threadIdx.x;
    const int n0  = blockIdx.x * 32;
    const int tx  = tid & 7;       // 8 col-groups of 4
    const int ty  = tid >> 3;      // 16 row-groups of 4

    float acc[4][4];
#pragma unroll
    for (int i = 0; i < 4; i++)
#pragma unroll
        for (int j = 0; j < 4; j++) acc[i][j] = 0.f;

    for (int k0 = 0; k0 < K; k0 += 32) {
        // Load A tile 64x32 (512 float4, 4 per thread), store transposed
#pragma unroll
        for (int r = 0; r < 4; r++) {
            int f  = tid + 128 * r;        // [0,512)
            int m  = f >> 3;
            int c4 = f & 7;
            float4 a = *(const float4*)(A + (size_t)m * K + k0 + c4 * 4);
            As[c4 * 4 + 0][m] = a.x;
            As[c4 * 4 + 1][m] = a.y;
            As[c4 * 4 + 2][m] = a.z;
            As[c4 * 4 + 3][m] = a.w;
        }
        // Load B tile 32x32 (256 float4, 2 per thread)
#pragma unroll
        for (int r = 0; r < 2; r++) {
            int f  = tid + 128 * r;        // [0,256)
            int kk = f >> 3;
            int c4 = f & 7;
            float4 b = *(const float4*)(B + (size_t)(k0 + kk) * N + n0 + c4 * 4);
            *(float4*)&Bs[kk][c4 * 4] = b;
        }
        __syncthreads();

#pragma unroll
        for (int kk = 0; kk < 32; kk++) {
            float4 a  = *(const float4*)&As[kk][ty * 4];
            float4 b4 = *(const float4*)&Bs[kk][tx * 4];
            float av[4] = {a.x, a.y, a.z, a.w};
            float bv[4] = {b4.x, b4.y, b4.z, b4.w};
#pragma unroll
            for (int i = 0; i < 4; i++)
#pragma unroll
                for (int j = 0; j < 4; j++)
                    acc[i][j] = fmaf(av[i], bv[j], acc[i][j]);
        }
        __syncthreads();
    }

    // Epilogue
    float4 bb = *(const float4*)(bias + n0 + tx * 4);
#pragma unroll
    for (int i = 0; i < 4; i++) {
        int m = ty * 4 + i;
        float v0 = acc[i][0] + bb.x;
        float v1 = acc[i][1] + bb.y;
        float v2 = acc[i][2] + bb.z;
        float v3 = acc[i][3] + bb.w;
        if (OP == 1) {
            v0 = fmaxf(v0, 0.f); v1 = fmaxf(v1, 0.f);
            v2 = fmaxf(v2, 0.f); v3 = fmaxf(v3, 0.f);
        }
        if (OP == 2) {
            float4 r4 = *(const float4*)(res + (size_t)m * N + n0 + tx * 4);
            v0 += r4.x; v1 += r4.y; v2 += r4.z; v3 += r4.w;
        }
        float4 out = make_float4(v0, v1, v2, v3);
        *(float4*)(C + (size_t)m * N + n0 + tx * 4) = out;
    }
}

// ---------------------------------------------------------------------------
// Attention decode: 1 block per (b,h). 128 threads = 4 warps.
// Warp processes rows t = w*4+j + 16*iter; lane covers 2 of 64 head dims.
// Online softmax in log2 domain. New token's k/v taken from g_qkv.
// ---------------------------------------------------------------------------
__global__ void __launch_bounds__(128)
attn_kernel(const float* __restrict__ qkv,
            const float* __restrict__ kc,
            const float* __restrict__ vc,
            const int*   __restrict__ kvlen,
            float* __restrict__ o)
{
    const int bh   = blockIdx.x;           // 0..1023
    const int b    = bh >> 4;
    const int h    = bh & 15;
    const int lane = threadIdx.x & 31;
    const int w    = threadIdx.x >> 5;     // 0..3

    const int len0 = kvlen[b];             // new token written at this index

    const float* qp = qkv + (size_t)b * 3072 + h * HDIM;
    const float2 q  = *(const float2*)(qp + 2 * lane);

    const size_t rowbase = ((size_t)(b * NHEAD + h)) * TMAX * HDIM;
    const float* kb = kc + rowbase;
    const float* vb = vc + rowbase;

    const float SCALE = 0.125f * 1.4426950408889634f;  // 1/sqrt(64) * log2(e)

    float m = -1e30f, l = 0.f, acc0 = 0.f, acc1 = 0.f;

    for (int base = w * 4; base < len0; base += 16) {
        float2 kf[4], vf[4];
#pragma unroll
        for (int j = 0; j < 4; j++) {
            int t = base + j;
            if (t < len0) {
                kf[j] = *(const float2*)(kb + (size_t)t * HDIM + 2 * lane);
                vf[j] = *(const float2*)(vb + (size_t)t * HDIM + 2 * lane);
            }
        }
#pragma unroll
        for (int j = 0; j < 4; j++) {
            int t = base + j;
            if (t < len0) {
                float s = fmaf(q.x, kf[j].x, q.y * kf[j].y);
#pragma unroll
                for (int off = 16; off > 0; off >>= 1)
                    s += __shfl_xor_sync(0xffffffffu, s, off);
                s *= SCALE;
                float mn   = fmaxf(m, s);
                float corr = exp2f(m - mn);
                float p    = exp2f(s - mn);
                l    = fmaf(l,    corr, p);
                acc0 = fmaf(acc0, corr, p * vf[j].x);
                acc1 = fmaf(acc1, corr, p * vf[j].y);
                m = mn;
            }
        }
    }

    // New token (position len0): k/v from the QKV projection scratch.
    if (w == 0) {
        const float* kn = qkv + (size_t)b * 3072 + DMODEL     + h * HDIM;
        const float* vn = qkv + (size_t)b * 3072 + 2 * DMODEL + h * HDIM;
        float2 kf = *(const float2*)(kn + 2 * lane);
        float2 vf = *(const float2*)(vn + 2 * lane);
        float s = fmaf(q.x, kf.x, q.y * kf.y);
#pragma unroll
        for (int off = 16; off > 0; off >>= 1)
            s += __shfl_xor_sync(0xffffffffu, s, off);
        s *= SCALE;
        float mn   = fmaxf(m, s);
        float corr = exp2f(m - mn);
        float p    = exp2f(s - mn);
        l    = fmaf(l,    corr, p);
        acc0 = fmaf(acc0, corr, p * vf.x);
        acc1 = fmaf(acc1, corr, p * vf.y);
        m = mn;
    }

    // Cross-warp combine
    __shared__ float sm[4], sl[4], sacc[4][HDIM];
    sacc[w][2 * lane]     = acc0;
    sacc[w][2 * lane + 1] = acc1;
    if (lane == 0) { sm[w] = m; sl[w] = l; }
    __syncthreads();

    if (threadIdx.x < HDIM) {
        int d = threadIdx.x;
        float M = fmaxf(fmaxf(sm[0], sm[1]), fmaxf(sm[2], sm[3]));
        float L = 0.f, O = 0.f;
#pragma unroll
        for (int ww = 0; ww < 4; ww++) {
            float c = exp2f(sm[ww] - M);
            L = fmaf(sl[ww], c, L);
            O = fmaf(sacc[ww][d], c, O);
        }
        o[(size_t)b * DMODEL + h * HDIM + d] = O / L;
    }
}

// ---------------------------------------------------------------------------
// LayerNorm: 1 block per row of 1024, 256 threads (4 elems each)
// ---------------------------------------------------------------------------
__global__ void __launch_bounds__(256)
ln_kernel(const float* __restrict__ x, const float* __restrict__ w,
          const float* __restrict__ bq, float* __restrict__ out)
{
    const int row = blockIdx.x;
    const float* xr = x + (size_t)row * DMODEL;
    const int tid = threadIdx.x;

    float v[4];
    float s = 0.f, ss = 0.f;
#pragma unroll
    for (int j = 0; j < 4; j++) {
        v[j] = xr[tid + 256 * j];
        s  += v[j];
        ss += v[j] * v[j];
    }
    // warp reduce
#pragma unroll
    for (int off = 16; off > 0; off >>= 1) {
        s  += __shfl_xor_sync(0xffffffffu, s,  off);
        ss += __shfl_xor_sync(0xffffffffu, ss, off);
    }
    __shared__ float rs[8], rss[8];
    int wid = tid >> 5, lane = tid & 31;
    if (lane == 0) { rs[wid] = s; rss[wid] = ss; }
    __syncthreads();
    __shared__ float s_mean, s_inv;
    if (tid == 0) {
        float S = 0.f, SS = 0.f;
#pragma unroll
        for (int i = 0; i < 8; i++) { S += rs[i]; SS += rss[i]; }
        float mean = S * (1.f / DMODEL);
        float var  = SS * (1.f / DMODEL) - mean * mean;
        s_mean = mean;
        s_inv  = rsqrtf(var + LN_EPS);
    }
    __syncthreads();
    float mean = s_mean, inv = s_inv;
#pragma unroll
    for (int j = 0; j < 4; j++) {
        int idx = tid + 256 * j;
        out[(size_t)row * DMODEL + idx] =
            (v[j] - mean) * inv * w[idx] + bq[idx];
    }
}

// ---------------------------------------------------------------------------
// Launch
// ---------------------------------------------------------------------------
extern "C" void kernel_launch(void* const* d_in, const int* in_sizes, int n_in,
                              void* d_out, int out_size)
{
    const float* x       = (const float*)d_in[0];
    const float* k_cache = (const float*)d_in[1];
    const float* v_cache = (const float*)d_in[2];
    // d_in[3] attn_mask (unused; equivalent to t <= kv_cache_len)
    const int*   kv_len  = (const int*)  d_in[4];
    // d_in[5] batch_indices (identity, unused)
    const float* qkv_w   = (const float*)d_in[6];
    const float* qkv_b   = (const float*)d_in[7];
    const float* out_w   = (const float*)d_in[8];
    const float* out_b   = (const float*)d_in[9];
    const float* ln1_w   = (const float*)d_in[10];
    const float* ln1_b   = (const float*)d_in[11];
    const float* ln2_w   = (const float*)d_in[12];
    const float* ln2_b   = (const float*)d_in[13];
    const float* mlp_w1  = (const float*)d_in[14];
    const float* mlp_b1  = (const float*)d_in[15];
    const float* mlp_w2  = (const float*)d_in[16];
    const float* mlp_b2  = (const float*)d_in[17];
    float* out = (float*)d_out;

    float *p_qkv, *p_o, *p_x1, *p_ln1, *p_h, *p_x2;
    cudaGetSymbolAddress((void**)&p_qkv, g_qkv);
    cudaGetSymbolAddress((void**)&p_o,   g_o);
    cudaGetSymbolAddress((void**)&p_x1,  g_x1);
    cudaGetSymbolAddress((void**)&p_ln1, g_ln1);
    cudaGetSymbolAddress((void**)&p_h,   g_h);
    cudaGetSymbolAddress((void**)&p_x2,  g_x2);

    // 1. QKV projection: [64,1024] @ [1024,3072]
    gemm64<0><<<3 * DMODEL / 32, 128>>>(x, qkv_w, qkv_b, nullptr, p_qkv,
                                        3 * DMODEL, DMODEL);
    // 2. Attention decode (reads new k/v from g_qkv; caches untouched)
    attn_kernel<<<BATCH * NHEAD, 128>>>(p_qkv, k_cache, v_cache, kv_len, p_o);
    // 3. Output projection + residual(x)
    gemm64<2><<<DMODEL / 32, 128>>>(p_o, out_w, out_b, x, p_x1,
                                    DMODEL, DMODEL);
    // 4. LN1
    ln_kernel<<<BATCH, 256>>>(p_x1, ln1_w, ln1_b, p_ln1);
    // 5. MLP up + ReLU: [64,1024] @ [1024,4096]
    gemm64<1><<<DFF / 32, 128>>>(p_ln1, mlp_w1, mlp_b1, nullptr, p_h,
                                 DFF, DMODEL);
    // 6. MLP down + residual(ln1): [64,4096] @ [4096,1024]
    gemm64<2><<<DMODEL / 32, 128>>>(p_h, mlp_w2, mlp_b2, p_ln1, p_x2,
                                    DMODEL, DFF);
    // 7. LN2 -> output
    ln_kernel<<<BATCH, 256>>>(p_x2, ln2_w, ln2_b, out);
}

// round 3
// speedup vs baseline: 1.7581x; 1.7581x over previous
#include <cuda_runtime.h>
#include <cuda_bf16.h>
#include <cstdint>
#include <math.h>

// ---------------------------------------------------------------------------
// Problem constants
// ---------------------------------------------------------------------------
#define BATCH 64
#define DMODEL 1024
#define NHEAD 16
#define HDIM 64
#define TMAX 2048
#define DFF 4096
#define LN_EPS 1e-5f

// Attention tiling
#define TS 128            // rows per tile
#define NST 3             // pipeline stages
#define ROWPITCH 68       // floats per smem row (64 + 4 pad, conflict-free)
#define TILE_F (TS * ROWPITCH)          // floats per K (or V) tile = 8704
#define STAGE_F (2 * TILE_F)            // K+V per stage = 17408

// smem float offsets
#define OFF_PARR (NST * STAGE_F)        // 52224, p[128]
#define OFF_QS   (OFF_PARR + 128)       // q scaled [64]
#define OFF_WMAX (OFF_QS + 64)          // [8]
#define OFF_WSUM (OFF_WMAX + 8)         // [8]
#define OFF_SCR  (OFF_WSUM + 8)         // [72] dot scratch
#define OFF_RED  (OFF_SCR + 72)         // [256] final reduce
#define SMEM_F   (OFF_RED + 256)
#define SMEM_BYTES (SMEM_F * 4)         // ~211 KB

// ---------------------------------------------------------------------------
// Scratch (device globals; no allocation allowed)
// ---------------------------------------------------------------------------
__device__ float g_qkv [BATCH * 3 * DMODEL];      // [64, 3072]
__device__ float g_o   [BATCH * DMODEL];          // attention output
__device__ float g_ln1 [BATCH * DMODEL];          // after LN1
__device__ float g_h   [BATCH * DFF];             // MLP hidden
__device__ float g_part[8 * BATCH * DMODEL];      // split-K partials (max S=8)

// ---------------------------------------------------------------------------
// cp.async helpers
// ---------------------------------------------------------------------------
__device__ __forceinline__ void cp_async16(unsigned int dst, const void* src) {
    asm volatile("cp.async.cg.shared.global [%0], [%1], 16;\n" :: "r"(dst), "l"(src));
}
__device__ __forceinline__ void cp_commit() {
    asm volatile("cp.async.commit_group;\n");
}
template<int N> __device__ __forceinline__ void cp_wait() {
    asm volatile("cp.async.wait_group %0;\n" :: "n"(N));
}

// ---------------------------------------------------------------------------
// GEMM: C[64,N] = A[64,K] @ B[K,N] (+bias) (+relu)
// BM=64, BN=32, BK=32, 128 threads, 4x4 micro-tile per thread.
// OP: 0 = bias, 1 = bias+relu
// ---------------------------------------------------------------------------
template<int OP>
__global__ void __launch_bounds__(128)
gemm64(const float* __restrict__ A, const float* __restrict__ B,
       const float* __restrict__ bias,
       float* __restrict__ C, int N, int K)
{
    __shared__ float As[32][68];
    __shared__ float Bs[32][32];

    const int tid = threadIdx.x;
    const int n0  = blockIdx.x * 32;
    const int tx  = tid & 7;
    const int ty  = tid >> 3;

    float acc[4][4];
#pragma unroll
    for (int i = 0; i < 4; i++)
#pragma unroll
        for (int j = 0; j < 4; j++) acc[i][j] = 0.f;

    for (int k0 = 0; k0 < K; k0 += 32) {
#pragma unroll
        for (int r = 0; r < 4; r++) {
            int f  = tid + 128 * r;
            int m  = f >> 3;
            int c4 = f & 7;
            float4 a = *(const float4*)(A + (size_t)m * K + k0 + c4 * 4);
            As[c4 * 4 + 0][m] = a.x;
            As[c4 * 4 + 1][m] = a.y;
            As[c4 * 4 + 2][m] = a.z;
            As[c4 * 4 + 3][m] = a.w;
        }
#pragma unroll
        for (int r = 0; r < 2; r++) {
            int f  = tid + 128 * r;
            int kk = f >> 3;
            int c4 = f & 7;
            float4 b = *(const float4*)(B + (size_t)(k0 + kk) * N + n0 + c4 * 4);
            *(float4*)&Bs[kk][c4 * 4] = b;
        }
        __syncthreads();

#pragma unroll
        for (int kk = 0; kk < 32; kk++) {
            float4 a  = *(const float4*)&As[kk][ty * 4];
            float4 b4 = *(const float4*)&Bs[kk][tx * 4];
            float av[4] = {a.x, a.y, a.z, a.w};
            float bv[4] = {b4.x, b4.y, b4.z, b4.w};
#pragma unroll
            for (int i = 0; i < 4; i++)
#pragma unroll
                for (int j = 0; j < 4; j++)
                    acc[i][j] = fmaf(av[i], bv[j], acc[i][j]);
        }
        __syncthreads();
    }

    float4 bb = *(const float4*)(bias + n0 + tx * 4);
#pragma unroll
    for (int i = 0; i < 4; i++) {
        int m = ty * 4 + i;
        float v0 = acc[i][0] + bb.x;
        float v1 = acc[i][1] + bb.y;
        float v2 = acc[i][2] + bb.z;
        float v3 = acc[i][3] + bb.w;
        if (OP == 1) {
            v0 = fmaxf(v0, 0.f); v1 = fmaxf(v1, 0.f);
            v2 = fmaxf(v2, 0.f); v3 = fmaxf(v3, 0.f);
        }
        *(float4*)(C + (size_t)m * N + n0 + tx * 4) = make_float4(v0, v1, v2, v3);
    }
}

// ---------------------------------------------------------------------------
// Split-K partial GEMM: part[s][64][N] = A[64, ks:ke] @ B[ks:ke, N]
// grid = (N/32, S)
// ---------------------------------------------------------------------------
__global__ void __launch_bounds__(128)
gemm64_part(const float* __restrict__ A, const float* __restrict__ B,
            float* __restrict__ part, int N, int kchunk)
{
    __shared__ float As[32][68];
    __shared__ float Bs[32][32];

    const int tid = threadIdx.x;
    const int n0  = blockIdx.x * 32;
    const int ks  = blockIdx.y * kchunk;
    const int ke  = ks + kchunk;
    const int K   = gridDim.y * kchunk;   // full K for A row stride
    const int tx  = tid & 7;
    const int ty  = tid >> 3;

    float acc[4][4];
#pragma unroll
    for (int i = 0; i < 4; i++)
#pragma unroll
        for (int j = 0; j < 4; j++) acc[i][j] = 0.f;

    for (int k0 = ks; k0 < ke; k0 += 32) {
#pragma unroll
        for (int r = 0; r < 4; r++) {
            int f  = tid + 128 * r;
            int m  = f >> 3;
            int c4 = f & 7;
            float4 a = *(const float4*)(A + (size_t)m * K + k0 + c4 * 4);
            As[c4 * 4 + 0][m] = a.x;
            As[c4 * 4 + 1][m] = a.y;
            As[c4 * 4 + 2][m] = a.z;
            As[c4 * 4 + 3][m] = a.w;
        }
#pragma unroll
        for (int r = 0; r < 2; r++) {
            int f  = tid + 128 * r;
            int kk = f >> 3;
            int c4 = f & 7;
            float4 b = *(const float4*)(B + (size_t)(k0 + kk) * N + n0 + c4 * 4);
            *(float4*)&Bs[kk][c4 * 4] = b;
        }
        __syncthreads();

#pragma unroll
        for (int kk = 0; kk < 32; kk++) {
            float4 a  = *(const float4*)&As[kk][ty * 4];
            float4 b4 = *(const float4*)&Bs[kk][tx * 4];
            float av[4] = {a.x, a.y, a.z, a.w};
            float bv[4] = {b4.x, b4.y, b4.z, b4.w};
#pragma unroll
            for (int i = 0; i < 4; i++)
#pragma unroll
                for (int j = 0; j < 4; j++)
                    acc[i][j] = fmaf(av[i], bv[j], acc[i][j]);
        }
        __syncthreads();
    }

    float* pout = part + (size_t)blockIdx.y * (64 * DMODEL);
#pragma unroll
    for (int i = 0; i < 4; i++) {
        int m = ty * 4 + i;
        *(float4*)(pout + (size_t)m * N + n0 + tx * 4) =
            make_float4(acc[i][0], acc[i][1], acc[i][2], acc[i][3]);
    }
}

// ---------------------------------------------------------------------------
// Fused: sum split-K partials + bias + residual, then LayerNorm.
// 1 block per row (64 rows), 256 threads, 4 cols/thread. N = 1024.
// ---------------------------------------------------------------------------
template<int S>
__global__ void __launch_bounds__(256)
reduce_ln(const float* __restrict__ part, const float* __restrict__ bias,
          const float* __restrict__ res,  const float* __restrict__ w,
          const float* __restrict__ bq,   float* __restrict__ out)
{
    const int row = blockIdx.x;
    const int tid = threadIdx.x;

    float v[4];
    float s = 0.f, ss = 0.f;
#pragma unroll
    for (int j = 0; j < 4; j++) {
        int col = tid + 256 * j;
        float x = bias[col] + res[(size_t)row * DMODEL + col];
#pragma unroll
        for (int sp = 0; sp < S; sp++)
            x += part[(size_t)sp * (64 * DMODEL) + (size_t)row * DMODEL + col];
        v[j] = x;
        s += x;
        ss += x * x;
    }
#pragma unroll
    for (int off = 16; off > 0; off >>= 1) {
        s  += __shfl_xor_sync(0xffffffffu, s,  off);
        ss += __shfl_xor_sync(0xffffffffu, ss, off);
    }
    __shared__ float rs[8], rss[8];
    int wid = tid >> 5, lane = tid & 31;
    if (lane == 0) { rs[wid] = s; rss[wid] = ss; }
    __syncthreads();
    __shared__ float s_mean, s_inv;
    if (tid == 0) {
        float S1 = 0.f, S2 = 0.f;
#pragma unroll
        for (int i = 0; i < 8; i++) { S1 += rs[i]; S2 += rss[i]; }
        float mean = S1 * (1.f / DMODEL);
        float var  = S2 * (1.f / DMODEL) - mean * mean;
        s_mean = mean;
        s_inv  = rsqrtf(var + LN_EPS);
    }
    __syncthreads();
    float mean = s_mean, inv = s_inv;
#pragma unroll
    for (int j = 0; j < 4; j++) {
        int col = tid + 256 * j;
        out[(size_t)row * DMODEL + col] = (v[j] - mean) * inv * w[col] + bq[col];
    }
}

// ---------------------------------------------------------------------------
// Attention v2: pipelined flash-decode.
// 1 block per (b,h), 256 threads, TS=128 row tiles, 3-stage cp.async pipeline.
// ---------------------------------------------------------------------------
__device__ __forceinline__ void issue_tile(float* sm, int buf,
                                           const float* kb, const float* vb,
                                           int t0, int tid)
{
    float* kd = sm + buf * STAGE_F;
    float* vd = kd + TILE_F;
    const float4* ks = (const float4*)(kb + (size_t)t0 * HDIM);
    const float4* vs = (const float4*)(vb + (size_t)t0 * HDIM);
#pragma unroll
    for (int it = 0; it < 8; it++) {
        int idx = it * 256 + tid;           // [0, 2048)
        int row = idx >> 4;                 // 16 float4 per row
        int c   = idx & 15;
        unsigned int dK = (unsigned int)__cvta_generic_to_shared(kd + row * ROWPITCH + c * 4);
        cp_async16(dK, ks + row * 16 + c);
        unsigned int dV = (unsigned int)__cvta_generic_to_shared(vd + row * ROWPITCH + c * 4);
        cp_async16(dV, vs + row * 16 + c);
    }
    cp_commit();
}

__global__ void __launch_bounds__(256, 1)
attn2_kernel(const float* __restrict__ qkv,
             const float* __restrict__ kc,
             const float* __restrict__ vc,
             const int*   __restrict__ kvlen,
             float* __restrict__ o)
{
    extern __shared__ float sm[];
    float* p_arr  = sm + OFF_PARR;
    float* q_s    = sm + OFF_QS;
    float* wmax   = sm + OFF_WMAX;
    float* wsum   = sm + OFF_WSUM;
    float* scr    = sm + OFF_SCR;
    float* red    = sm + OFF_RED;

    const int bh   = blockIdx.x;
    const int b    = bh >> 4;
    const int h    = bh & 15;
    const int tid  = threadIdx.x;
    const int lane = tid & 31;
    const int w    = tid >> 5;

    const int len0 = kvlen[b];
    const float SCALE = 0.125f * 1.4426950408889634f;  // 1/sqrt(64)*log2e

    const float* qp = qkv + (size_t)b * 3072 + h * HDIM;
    if (tid < HDIM) q_s[tid] = qp[tid] * SCALE;

    const size_t rowbase = ((size_t)(b * NHEAD + h)) * TMAX * HDIM;
    const float* kb = kc + rowbase;
    const float* vb = vc + rowbase;

    const int ntiles = (len0 + TS - 1) / TS;   // >= 8 always

    // Prologue: fill the pipeline
#pragma unroll
    for (int s = 0; s < NST; s++)
        if (s < ntiles) issue_tile(sm, s, kb, vb, s * TS, tid);
    __syncthreads();   // q_s visible

    // q in registers for this thread's 32-dim half
    const int r    = w * 16 + (lane & 15);   // score row within tile
    const int half = lane >> 4;
    float4 qv[8];
#pragma unroll
    for (int j = 0; j < 8; j++)
        qv[j] = *(const float4*)&q_s[half * 32 + j * 4];

    const int d  = tid & 63;     // accumulation dim
    const int ch = tid >> 6;     // row chunk (4 chunks of 32)

    float m_run = -1e30f, l_run = 0.f, acc = 0.f;

    for (int i = 0; i < ntiles; i++) {
        int issued = (i + NST < ntiles) ? (i + NST) : ntiles;
        int pending = issued - i - 1;        // groups allowed pending
        if (pending >= 2)      cp_wait<2>();
        else if (pending == 1) cp_wait<1>();
        else                   cp_wait<0>();
        __syncthreads();

        const float* Ks = sm + (i % NST) * STAGE_F;
        const float* Vs = Ks + TILE_F;

        // --- scores: each thread dots a 32-dim half of its row ---
        float s = 0.f;
        const float4* kr = (const float4*)&Ks[r * ROWPITCH + half * 32];
#pragma unroll
        for (int j = 0; j < 8; j++) {
            float4 kf = kr[j];
            s = fmaf(qv[j].x, kf.x,
                fmaf(qv[j].y, kf.y,
                fmaf(qv[j].z, kf.z,
                fmaf(qv[j].w, kf.w, s))));
        }
        s += __shfl_xor_sync(0xffffffffu, s, 16);   // combine halves
        int t = i * TS + r;
        if (t >= len0) s = -1e30f;

        float wm = s;
#pragma unroll
        for (int off = 8; off > 0; off >>= 1)
            wm = fmaxf(wm, __shfl_xor_sync(0xffffffffu, wm, off));
        if (lane == 0) wmax[w] = wm;
        __syncthreads();

        float mt = wmax[0];
#pragma unroll
        for (int k = 1; k < 8; k++) mt = fmaxf(mt, wmax[k]);
        float m_new = fmaxf(m_run, mt);
        float corr  = exp2f(m_run - m_new);

        float p = exp2f(s - m_new);                 // 0 for masked rows
        if (lane < 16) p_arr[r] = p;
        float ps = (lane < 16) ? p : 0.f;
#pragma unroll
        for (int off = 16; off > 0; off >>= 1)
            ps += __shfl_xor_sync(0xffffffffu, ps, off);
        if (lane == 0) wsum[w] = ps;
        __syncthreads();

        float tsum = 0.f;
#pragma unroll
        for (int k = 0; k < 8; k++) tsum += wsum[k];
        l_run = l_run * corr + tsum;
        m_run = m_new;

        // --- accumulate O: thread owns (dim d, row-chunk ch) ---
        acc *= corr;
        const float* vcol = Vs + ch * 32 * ROWPITCH + d;
        const float* pp   = p_arr + ch * 32;
        float a0 = 0.f, a1 = 0.f;
#pragma unroll
        for (int rr = 0; rr < 32; rr += 2) {
            a0 = fmaf(pp[rr],     vcol[(size_t)rr * ROWPITCH],       a0);
            a1 = fmaf(pp[rr + 1], vcol[(size_t)(rr + 1) * ROWPITCH], a1);
        }
        acc += a0 + a1;
        __syncthreads();    // everyone done reading stage i buffers

        if (i + NST < ntiles)
            issue_tile(sm, i % NST, kb, vb, (i + NST) * TS, tid);
    }

    // --- new token (position len0): k/v from QKV scratch ---
    const float* kn = qkv + (size_t)b * 3072 + DMODEL     + h * HDIM;
    const float* vn = qkv + (size_t)b * 3072 + 2 * DMODEL + h * HDIM;
    if (tid < HDIM) scr[tid] = q_s[tid] * kn[tid];
    __syncthreads();
    if (w == 0) {
        float x = scr[lane] + scr[lane + 32];
#pragma unroll
        for (int off = 16; off > 0; off >>= 1)
            x += __shfl_xor_sync(0xffffffffu, x, off);
        if (lane == 0) scr[64] = x;
    }
    __syncthreads();
    {
        float snew  = scr[64];
        float m_new = fmaxf(m_run, snew);
        float corr  = exp2f(m_run - m_new);
        float pn    = exp2f(snew - m_new);
        l_run = l_run * corr + pn;
        acc *= corr;
        if (ch == 0) acc += pn * vn[d];
    }

    // --- combine 4 chunks, write output ---
    red[ch * 64 + d] = acc;
    __syncthreads();
    if (tid < HDIM) {
        float O = red[tid] + red[64 + tid] + red[128 + tid] + red[192 + tid];
        o[(size_t)b * DMODEL + h * HDIM + tid] = O / l_run;
    }
}

// ---------------------------------------------------------------------------
// Launch
// ---------------------------------------------------------------------------
extern "C" void kernel_launch(void* const* d_in, const int* in_sizes, int n_in,
                              void* d_out, int out_size)
{
    const float* x       = (const float*)d_in[0];
    const float* k_cache = (const float*)d_in[1];
    const float* v_cache = (const float*)d_in[2];
    // d_in[3] attn_mask (unused; equivalent to t <= kv_cache_len)
    const int*   kv_len  = (const int*)  d_in[4];
    // d_in[5] batch_indices (identity, unused)
    const float* qkv_w   = (const float*)d_in[6];
    const float* qkv_b   = (const float*)d_in[7];
    const float* out_w   = (const float*)d_in[8];
    const float* out_b   = (const float*)d_in[9];
    const float* ln1_w   = (const float*)d_in[10];
    const float* ln1_b   = (const float*)d_in[11];
    const float* ln2_w   = (const float*)d_in[12];
    const float* ln2_b   = (const float*)d_in[13];
    const float* mlp_w1  = (const float*)d_in[14];
    const float* mlp_b1  = (const float*)d_in[15];
    const float* mlp_w2  = (const float*)d_in[16];
    const float* mlp_b2  = (const float*)d_in[17];
    float* out = (float*)d_out;

    float *p_qkv, *p_o, *p_ln1, *p_h, *p_part;
    cudaGetSymbolAddress((void**)&p_qkv,  g_qkv);
    cudaGetSymbolAddress((void**)&p_o,    g_o);
    cudaGetSymbolAddress((void**)&p_ln1,  g_ln1);
    cudaGetSymbolAddress((void**)&p_h,    g_h);
    cudaGetSymbolAddress((void**)&p_part, g_part);

    cudaFuncSetAttribute(attn2_kernel,
                         cudaFuncAttributeMaxDynamicSharedMemorySize, SMEM_BYTES);

    // 1. QKV projection: [64,1024] @ [1024,3072]
    gemm64<0><<<3 * DMODEL / 32, 128>>>(x, qkv_w, qkv_b, p_qkv, 3 * DMODEL, DMODEL);

    // 2. Attention decode (pipelined)
    attn2_kernel<<<BATCH * NHEAD, 256, SMEM_BYTES>>>(p_qkv, k_cache, v_cache,
                                                     kv_len, p_o);

    // 3. Output projection, split-K=4 (partials)
    gemm64_part<<<dim3(DMODEL / 32, 4), 128>>>(p_o, out_w, p_part, DMODEL, 256);

    // 4. reduce + bias + residual(x) + LN1 -> g_ln1
    reduce_ln<4><<<BATCH, 256>>>(p_part, out_b, x, ln1_w, ln1_b, p_ln1);

    // 5. MLP up + ReLU: [64,1024] @ [1024,4096]
    gemm64<1><<<DFF / 32, 128>>>(p_ln1, mlp_w1, mlp_b1, p_h, DFF, DMODEL);

    // 6. MLP down, split-K=8 (partials)
    gemm64_part<<<dim3(DMODEL / 32, 8), 128>>>(p_h, mlp_w2, p_part, DMODEL, 512);

    // 7. reduce + bias + residual(ln1) + LN2 -> out
    reduce_ln<8><<<BATCH, 256>>>(p_part, mlp_b2, p_ln1, ln2_w, ln2_b, out);
}

// round 5
// speedup vs baseline: 1.7668x; 1.0049x over previous
#include <cuda_runtime.h>
#include <cuda_bf16.h>
#include <cstdint>
#include <math.h>

// ---------------------------------------------------------------------------
// Problem constants
// ---------------------------------------------------------------------------
#define BATCH 64
#define DMODEL 1024
#define NHEAD 16
#define HDIM 64
#define TMAX 2048
#define DFF 4096
#define LN_EPS 1e-5f

// Attention tiling
#define TS 64             // rows per tile
#define NST 3             // pipeline stages
#define ROWPITCH 68       // floats per smem row (64 + 4 pad)
#define TILE_F (TS * ROWPITCH)          // 4352 floats per K (or V) tile
#define STAGE_F (2 * TILE_F)            // K+V per stage = 8704 floats
#define SPLIT 4
#define SPLIT_ROWS 512

// smem float offsets
#define OFF_PARR (NST * STAGE_F)        // 26112
#define OFF_QS   (OFF_PARR + TS)        // +64
#define OFF_WMAX (OFF_QS + 64)          // [8]
#define OFF_WSUM (OFF_WMAX + 8)         // [8]
#define OFF_RED  (OFF_WSUM + 8)         // [256]
#define SMEM_F   (OFF_RED + 256)
#define SMEM_BYTES (SMEM_F * 4)         // ~104 KB -> 2 CTAs/SM

// ---------------------------------------------------------------------------
// Scratch (device globals; no allocation allowed)
// ---------------------------------------------------------------------------
__device__ float g_qkv  [BATCH * 3 * DMODEL];     // [64, 3072]
__device__ float g_o    [BATCH * DMODEL];         // attention output
__device__ float g_ln1  [BATCH * DMODEL];         // after LN1
__device__ float g_h    [BATCH * DFF];            // MLP hidden
__device__ float g_part [8 * BATCH * DMODEL];     // split-K GEMM partials
__device__ float g_pattn[BATCH * NHEAD * SPLIT * 68];  // attn partials (m,l,O[64])

// ---------------------------------------------------------------------------
// cp.async helpers
// ---------------------------------------------------------------------------
__device__ __forceinline__ void cp_async16(unsigned int dst, const void* src) {
    asm volatile("cp.async.cg.shared.global [%0], [%1], 16;\n" :: "r"(dst), "l"(src));
}
__device__ __forceinline__ void cp_commit() {
    asm volatile("cp.async.commit_group;\n");
}
template<int N> __device__ __forceinline__ void cp_wait() {
    asm volatile("cp.async.wait_group %0;\n" :: "n"(N));
}

// ---------------------------------------------------------------------------
// GEMM: C[64,N] = A[64,K] @ B[K,N] (+bias) (+relu)
// ---------------------------------------------------------------------------
template<int OP>
__global__ void __launch_bounds__(128)
gemm64(const float* __restrict__ A, const float* __restrict__ B,
       const float* __restrict__ bias,
       float* __restrict__ C, int N, int K)
{
    __shared__ float As[32][68];
    __shared__ float Bs[32][32];

    const int tid = threadIdx.x;
    const int n0  = blockIdx.x * 32;
    const int tx  = tid & 7;
    const int ty  = tid >> 3;

    float acc[4][4];
#pragma unroll
    for (int i = 0; i < 4; i++)
#pragma unroll
        for (int j = 0; j < 4; j++) acc[i][j] = 0.f;

    for (int k0 = 0; k0 < K; k0 += 32) {
#pragma unroll
        for (int r = 0; r < 4; r++) {
            int f  = tid + 128 * r;
            int m  = f >> 3;
            int c4 = f & 7;
            float4 a = *(const float4*)(A + (size_t)m * K + k0 + c4 * 4);
            As[c4 * 4 + 0][m] = a.x;
            As[c4 * 4 + 1][m] = a.y;
            As[c4 * 4 + 2][m] = a.z;
            As[c4 * 4 + 3][m] = a.w;
        }
#pragma unroll
        for (int r = 0; r < 2; r++) {
            int f  = tid + 128 * r;
            int kk = f >> 3;
            int c4 = f & 7;
            float4 b = *(const float4*)(B + (size_t)(k0 + kk) * N + n0 + c4 * 4);
            *(float4*)&Bs[kk][c4 * 4] = b;
        }
        __syncthreads();

#pragma unroll
        for (int kk = 0; kk < 32; kk++) {
            float4 a  = *(const float4*)&As[kk][ty * 4];
            float4 b4 = *(const float4*)&Bs[kk][tx * 4];
            float av[4] = {a.x, a.y, a.z, a.w};
            float bv[4] = {b4.x, b4.y, b4.z, b4.w};
#pragma unroll
            for (int i = 0; i < 4; i++)
#pragma unroll
                for (int j = 0; j < 4; j++)
                    acc[i][j] = fmaf(av[i], bv[j], acc[i][j]);
        }
        __syncthreads();
    }

    float4 bb = *(const float4*)(bias + n0 + tx * 4);
#pragma unroll
    for (int i = 0; i < 4; i++) {
        int m = ty * 4 + i;
        float v0 = acc[i][0] + bb.x;
        float v1 = acc[i][1] + bb.y;
        float v2 = acc[i][2] + bb.z;
        float v3 = acc[i][3] + bb.w;
        if (OP == 1) {
            v0 = fmaxf(v0, 0.f); v1 = fmaxf(v1, 0.f);
            v2 = fmaxf(v2, 0.f); v3 = fmaxf(v3, 0.f);
        }
        *(float4*)(C + (size_t)m * N + n0 + tx * 4) = make_float4(v0, v1, v2, v3);
    }
}

// ---------------------------------------------------------------------------
// Split-K partial GEMM: part[s][64][N] = A[64, ks:ke] @ B[ks:ke, N]
// ---------------------------------------------------------------------------
__global__ void __launch_bounds__(128)
gemm64_part(const float* __restrict__ A, const float* __restrict__ B,
            float* __restrict__ part, int N, int kchunk)
{
    __shared__ float As[32][68];
    __shared__ float Bs[32][32];

    const int tid = threadIdx.x;
    const int n0  = blockIdx.x * 32;
    const int ks  = blockIdx.y * kchunk;
    const int ke  = ks + kchunk;
    const int K   = gridDim.y * kchunk;
    const int tx  = tid & 7;
    const int ty  = tid >> 3;

    float acc[4][4];
#pragma unroll
    for (int i = 0; i < 4; i++)
#pragma unroll
        for (int j = 0; j < 4; j++) acc[i][j] = 0.f;

    for (int k0 = ks; k0 < ke; k0 += 32) {
#pragma unroll
        for (int r = 0; r < 4; r++) {
            int f  = tid + 128 * r;
            int m  = f >> 3;
            int c4 = f & 7;
            float4 a = *(const float4*)(A + (size_t)m * K + k0 + c4 * 4);
            As[c4 * 4 + 0][m] = a.x;
            As[c4 * 4 + 1][m] = a.y;
            As[c4 * 4 + 2][m] = a.z;
            As[c4 * 4 + 3][m] = a.w;
        }
#pragma unroll
        for (int r = 0; r < 2; r++) {
            int f  = tid + 128 * r;
            int kk = f >> 3;
            int c4 = f & 7;
            float4 b = *(const float4*)(B + (size_t)(k0 + kk) * N + n0 + c4 * 4);
            *(float4*)&Bs[kk][c4 * 4] = b;
        }
        __syncthreads();

#pragma unroll
        for (int kk = 0; kk < 32; kk++) {
            float4 a  = *(const float4*)&As[kk][ty * 4];
            float4 b4 = *(const float4*)&Bs[kk][tx * 4];
            float av[4] = {a.x, a.y, a.z, a.w};
            float bv[4] = {b4.x, b4.y, b4.z, b4.w};
#pragma unroll
            for (int i = 0; i < 4; i++)
#pragma unroll
                for (int j = 0; j < 4; j++)
                    acc[i][j] = fmaf(av[i], bv[j], acc[i][j]);
        }
        __syncthreads();
    }

    float* pout = part + (size_t)blockIdx.y * (64 * DMODEL);
#pragma unroll
    for (int i = 0; i < 4; i++) {
        int m = ty * 4 + i;
        *(float4*)(pout + (size_t)m * N + n0 + tx * 4) =
            make_float4(acc[i][0], acc[i][1], acc[i][2], acc[i][3]);
    }
}

// ---------------------------------------------------------------------------
// Fused: sum split-K partials + bias + residual, then LayerNorm.
// ---------------------------------------------------------------------------
template<int S>
__global__ void __launch_bounds__(256)
reduce_ln(const float* __restrict__ part, const float* __restrict__ bias,
          const float* __restrict__ res,  const float* __restrict__ w,
          const float* __restrict__ bq,   float* __restrict__ out)
{
    const int row = blockIdx.x;
    const int tid = threadIdx.x;

    float v[4];
    float s = 0.f, ss = 0.f;
#pragma unroll
    for (int j = 0; j < 4; j++) {
        int col = tid + 256 * j;
        float x = bias[col] + res[(size_t)row * DMODEL + col];
#pragma unroll
        for (int sp = 0; sp < S; sp++)
            x += part[(size_t)sp * (64 * DMODEL) + (size_t)row * DMODEL + col];
        v[j] = x;
        s += x;
        ss += x * x;
    }
#pragma unroll
    for (int off = 16; off > 0; off >>= 1) {
        s  += __shfl_xor_sync(0xffffffffu, s,  off);
        ss += __shfl_xor_sync(0xffffffffu, ss, off);
    }
    __shared__ float rs[8], rss[8];
    int wid = tid >> 5, lane = tid & 31;
    if (lane == 0) { rs[wid] = s; rss[wid] = ss; }
    __syncthreads();
    __shared__ float s_mean, s_inv;
    if (tid == 0) {
        float S1 = 0.f, S2 = 0.f;
#pragma unroll
        for (int i = 0; i < 8; i++) { S1 += rs[i]; S2 += rss[i]; }
        float mean = S1 * (1.f / DMODEL);
        float var  = S2 * (1.f / DMODEL) - mean * mean;
        s_mean = mean;
        s_inv  = rsqrtf(var + LN_EPS);
    }
    __syncthreads();
    float mean = s_mean, inv = s_inv;
#pragma unroll
    for (int j = 0; j < 4; j++) {
        int col = tid + 256 * j;
        out[(size_t)row * DMODEL + col] = (v[j] - mean) * inv * w[col] + bq[col];
    }
}

// ---------------------------------------------------------------------------
// Attention v3: split-KV pipelined flash-decode.
// grid (BATCH*NHEAD, SPLIT); block 256 thr; TS=64; 2 CTAs/SM.
// Each block handles rows [sp*512, min((sp+1)*512, len)) of one (b,h).
// ---------------------------------------------------------------------------
__device__ __forceinline__ void issue_tile64(float* sm, int buf,
                                             const float* kb, const float* vb,
                                             int t0, int tid)
{
    float* kd = sm + buf * STAGE_F;
    float* vd = kd + TILE_F;
    const float4* ks = (const float4*)(kb + (size_t)t0 * HDIM);
    const float4* vs = (const float4*)(vb + (size_t)t0 * HDIM);
#pragma unroll
    for (int it = 0; it < 4; it++) {
        int idx = it * 256 + tid;           // [0, 1024)
        int row = idx >> 4;                 // 16 float4 per row
        int c   = idx & 15;
        unsigned int dK = (unsigned int)__cvta_generic_to_shared(kd + row * ROWPITCH + c * 4);
        cp_async16(dK, ks + row * 16 + c);
        unsigned int dV = (unsigned int)__cvta_generic_to_shared(vd + row * ROWPITCH + c * 4);
        cp_async16(dV, vs + row * 16 + c);
    }
    cp_commit();
}

__global__ void __launch_bounds__(256, 2)
attn3_kernel(const float* __restrict__ qkv,
             const float* __restrict__ kc,
             const float* __restrict__ vc,
             const int*   __restrict__ kvlen,
             float* __restrict__ part)
{
    extern __shared__ float sm[];
    float* p_arr = sm + OFF_PARR;
    float* q_s   = sm + OFF_QS;
    float* wmax  = sm + OFF_WMAX;
    float* wsum  = sm + OFF_WSUM;
    float* red   = sm + OFF_RED;

    const int bh   = blockIdx.x;
    const int sp   = blockIdx.y;
    const int b    = bh >> 4;
    const int h    = bh & 15;
    const int tid  = threadIdx.x;
    const int lane = tid & 31;
    const int w    = tid >> 5;

    const int len   = kvlen[b];
    const int start = sp * SPLIT_ROWS;
    if (start >= len) return;
    const int end    = (start + SPLIT_ROWS < len) ? (start + SPLIT_ROWS) : len;
    const int ntiles = (end - start + TS - 1) / TS;   // 1..8

    const float SCALE = 0.125f * 1.4426950408889634f;

    const float* qp = qkv + (size_t)b * 3072 + h * HDIM;
    if (tid < HDIM) q_s[tid] = qp[tid] * SCALE;

    const size_t rowbase = ((size_t)(b * NHEAD + h)) * TMAX * HDIM;
    const float* kb = kc + rowbase + (size_t)start * HDIM;
    const float* vb = vc + rowbase + (size_t)start * HDIM;

#pragma unroll
    for (int s = 0; s < NST; s++)
        if (s < ntiles) issue_tile64(sm, s, kb, vb, s * TS, tid);
    __syncthreads();   // q_s visible

    // score layout: 4 threads per row, 16 dims each
    const int r  = tid >> 2;
    const int qr = tid & 3;
    float4 qv[4];
#pragma unroll
    for (int j = 0; j < 4; j++)
        qv[j] = *(const float4*)&q_s[qr * 16 + j * 4];

    // accumulation layout: thread owns (dim d, 16-row chunk ch)
    const int d  = tid & 63;
    const int ch = tid >> 6;

    float m_run = -1e30f, l_run = 0.f, acc = 0.f;

    for (int i = 0; i < ntiles; i++) {
        int issued  = (i + NST < ntiles) ? (i + NST) : ntiles;
        int pending = issued - i - 1;
        if (pending >= 2)      cp_wait<2>();
        else if (pending == 1) cp_wait<1>();
        else                   cp_wait<0>();
        __syncthreads();

        const float* Ks = sm + (i % NST) * STAGE_F;
        const float* Vs = Ks + TILE_F;

        // scores
        float s = 0.f;
        const float4* kr = (const float4*)&Ks[r * ROWPITCH + qr * 16];
#pragma unroll
        for (int j = 0; j < 4; j++) {
            float4 kf = kr[j];
            s = fmaf(qv[j].x, kf.x,
                fmaf(qv[j].y, kf.y,
                fmaf(qv[j].z, kf.z,
                fmaf(qv[j].w, kf.w, s))));
        }
        s += __shfl_xor_sync(0xffffffffu, s, 1);
        s += __shfl_xor_sync(0xffffffffu, s, 2);   // full row dot, dup x4

        int t = start + i * TS + r;
        if (t >= end) s = -1e30f;

        // warp max over its 8 rows
        float wm = s;
        wm = fmaxf(wm, __shfl_xor_sync(0xffffffffu, wm, 4));
        wm = fmaxf(wm, __shfl_xor_sync(0xffffffffu, wm, 8));
        wm = fmaxf(wm, __shfl_xor_sync(0xffffffffu, wm, 16));
        if (lane == 0) wmax[w] = wm;
        __syncthreads();

        float mt = wmax[0];
#pragma unroll
        for (int k = 1; k < 8; k++) mt = fmaxf(mt, wmax[k]);
        float m_new = fmaxf(m_run, mt);
        float corr  = exp2f(m_run - m_new);

        float p = exp2f(s - m_new);
        if (qr == 0) p_arr[r] = p;
        // row-sum over warp's 8 rows (p dup within quad; xor 4,8,16 sums quads)
        float ps = p;
        ps += __shfl_xor_sync(0xffffffffu, ps, 4);
        ps += __shfl_xor_sync(0xffffffffu, ps, 8);
        ps += __shfl_xor_sync(0xffffffffu, ps, 16);
        if (lane == 0) wsum[w] = ps;
        __syncthreads();

        float tsum = wsum[0];
#pragma unroll
        for (int k = 1; k < 8; k++) tsum += wsum[k];
        l_run = l_run * corr + tsum;
        m_run = m_new;

        // V accumulation
        acc *= corr;
        const float* vcol = Vs + ch * 16 * ROWPITCH + d;
        const float* pp   = p_arr + ch * 16;
#pragma unroll
        for (int rr = 0; rr < 16; rr++)
            acc = fmaf(pp[rr], vcol[(size_t)rr * ROWPITCH], acc);
        __syncthreads();

        if (i + NST < ntiles)
            issue_tile64(sm, i % NST, kb, vb, (i + NST) * TS, tid);
    }

    // reduce 4 chunks, write partial (m, l, O[64])
    red[tid] = acc;
    __syncthreads();
    if (tid < HDIM) {
        float O = red[tid] + red[64 + tid] + red[128 + tid] + red[192 + tid];
        float* po = part + (size_t)(bh * SPLIT + sp) * 68;
        po[2 + tid] = O;
        if (tid == 0) { po[0] = m_run; po[1] = l_run; }
    }
}

// ---------------------------------------------------------------------------
// Combine split partials + new-token term -> o. grid 1024, 64 threads.
// ---------------------------------------------------------------------------
__global__ void __launch_bounds__(64)
attn_combine(const float* __restrict__ qkv, const float* __restrict__ part,
             const int* __restrict__ kvlen, float* __restrict__ o)
{
    const int bh = blockIdx.x;
    const int b  = bh >> 4;
    const int h  = bh & 15;
    const int d  = threadIdx.x;
    const int len  = kvlen[b];
    const int nact = (len + SPLIT_ROWS - 1) / SPLIT_ROWS;

    const float* qp = qkv + (size_t)b * 3072 + h * HDIM;
    const float* kn = qkv + (size_t)b * 3072 + DMODEL     + h * HDIM;
    const float* vn = qkv + (size_t)b * 3072 + 2 * DMODEL + h * HDIM;

    __shared__ float scr[64];
    __shared__ float snew_sh;
    scr[d] = qp[d] * kn[d];
    __syncthreads();
    if (d < 32) {
        float x = scr[d] + scr[d + 32];
#pragma unroll
        for (int off = 16; off > 0; off >>= 1)
            x += __shfl_xor_sync(0xffffffffu, x, off);
        if (d == 0) snew_sh = x * 0.125f * 1.4426950408889634f;
    }
    __syncthreads();

    float snew = snew_sh;
    float ms[SPLIT], ls[SPLIT];
    float M = snew;
    for (int s = 0; s < nact; s++) {
        const float* po = part + (size_t)(bh * SPLIT + s) * 68;
        ms[s] = po[0];
        ls[s] = po[1];
        M = fmaxf(M, ms[s]);
    }
    float pn = exp2f(snew - M);
    float L  = pn;
    float O  = pn * vn[d];
    for (int s = 0; s < nact; s++) {
        float c = exp2f(ms[s] - M);
        L = fmaf(ls[s], c, L);
        O = fmaf(part[(size_t)(bh * SPLIT + s) * 68 + 2 + d], c, O);
    }
    o[(size_t)b * DMODEL + h * HDIM + d] = O / L;
}

// ---------------------------------------------------------------------------
// Launch
// ---------------------------------------------------------------------------
extern "C" void kernel_launch(void* const* d_in, const int* in_sizes, int n_in,
                              void* d_out, int out_size)
{
    const float* x       = (const float*)d_in[0];
    const float* k_cache = (const float*)d_in[1];
    const float* v_cache = (const float*)d_in[2];
    // d_in[3] attn_mask (unused; equivalent to t <= kv_cache_len)
    const int*   kv_len  = (const int*)  d_in[4];
    // d_in[5] batch_indices (identity, unused)
    const float* qkv_w   = (const float*)d_in[6];
    const float* qkv_b   = (const float*)d_in[7];
    const float* out_w   = (const float*)d_in[8];
    const float* out_b   = (const float*)d_in[9];
    const float* ln1_w   = (const float*)d_in[10];
    const float* ln1_b   = (const float*)d_in[11];
    const float* ln2_w   = (const float*)d_in[12];
    const float* ln2_b   = (const float*)d_in[13];
    const float* mlp_w1  = (const float*)d_in[14];
    const float* mlp_b1  = (const float*)d_in[15];
    const float* mlp_w2  = (const float*)d_in[16];
    const float* mlp_b2  = (const float*)d_in[17];
    float* out = (float*)d_out;

    float *p_qkv, *p_o, *p_ln1, *p_h, *p_part, *p_pattn;
    cudaGetSymbolAddress((void**)&p_qkv,   g_qkv);
    cudaGetSymbolAddress((void**)&p_o,     g_o);
    cudaGetSymbolAddress((void**)&p_ln1,   g_ln1);
    cudaGetSymbolAddress((void**)&p_h,     g_h);
    cudaGetSymbolAddress((void**)&p_part,  g_part);
    cudaGetSymbolAddress((void**)&p_pattn, g_pattn);

    cudaFuncSetAttribute(attn3_kernel,
                         cudaFuncAttributeMaxDynamicSharedMemorySize, SMEM_BYTES);

    // 1. QKV projection: [64,1024] @ [1024,3072]
    gemm64<0><<<3 * DMODEL / 32, 128>>>(x, qkv_w, qkv_b, p_qkv, 3 * DMODEL, DMODEL);

    // 2a. Attention decode, split-KV x4 -> partials
    attn3_kernel<<<dim3(BATCH * NHEAD, SPLIT), 256, SMEM_BYTES>>>(
        p_qkv, k_cache, v_cache, kv_len, p_pattn);

    // 2b. Combine partials + new token -> o
    attn_combine<<<BATCH * NHEAD, 64>>>(p_qkv, p_pattn, kv_len, p_o);

    // 3. Output projection, split-K=4 (partials)
    gemm64_part<<<dim3(DMODEL / 32, 4), 128>>>(p_o, out_w, p_part, DMODEL, 256);

    // 4. reduce + bias + residual(x) + LN1 -> g_ln1
    reduce_ln<4><<<BATCH, 256>>>(p_part, out_b, x, ln1_w, ln1_b, p_ln1);

    // 5. MLP up + ReLU: [64,1024] @ [1024,4096]
    gemm64<1><<<DFF / 32, 128>>>(p_ln1, mlp_w1, mlp_b1, p_h, DFF, DMODEL);

    // 6. MLP down, split-K=8 (partials)
    gemm64_part<<<dim3(DMODEL / 32, 8), 128>>>(p_h, mlp_w2, p_part, DMODEL, 512);

    // 7. reduce + bias + residual(ln1) + LN2 -> out
    reduce_ln<8><<<BATCH, 256>>>(p_part, mlp_b2, p_ln1, ln2_w, ln2_b, out);
}

// round 6
// speedup vs baseline: 2.3957x; 1.3560x over previous
#include <cuda_runtime.h>
#include <cuda_bf16.h>
#include <cstdint>
#include <math.h>

// ---------------------------------------------------------------------------
// Problem constants
// ---------------------------------------------------------------------------
#define BATCH 64
#define DMODEL 1024
#define NHEAD 16
#define HDIM 64
#define TMAX 2048
#define DFF 4096
#define LN_EPS 1e-5f

// Attention tiling (unchanged from R5)
#define TS 64
#define NST 3
#define ROWPITCH 68
#define TILE_F (TS * ROWPITCH)
#define STAGE_F (2 * TILE_F)
#define SPLIT 4
#define SPLIT_ROWS 512

#define OFF_PARR (NST * STAGE_F)
#define OFF_QS   (OFF_PARR + TS)
#define OFF_WMAX (OFF_QS + 64)
#define OFF_WSUM (OFF_WMAX + 8)
#define OFF_RED  (OFF_WSUM + 8)
#define SMEM_F   (OFF_RED + 256)
#define SMEM_BYTES (SMEM_F * 4)

// GEMM tiling: BM=64, BN=32, BK=64, 3-stage cp.async pipeline
#define G_A_F   4096          // 64k x 64m floats per A stage
#define G_B_F   2048          // 64k x 32n floats per B stage
#define G_STG_F 6144
#define G_NST   3
#define G_SMEM_BYTES (G_NST * G_STG_F * 4)   // 73728

// ---------------------------------------------------------------------------
// Scratch (device globals; no allocation allowed)
// ---------------------------------------------------------------------------
__device__ float g_xT   [DMODEL * BATCH];         // x transposed [1024][64]
__device__ float g_qkv  [BATCH * 3 * DMODEL];     // [64][3072]
__device__ float g_oT   [DMODEL * BATCH];         // attn out transposed [1024][64]
__device__ float g_ln1  [BATCH * DMODEL];         // ln1 normal
__device__ float g_ln1T [DMODEL * BATCH];         // ln1 transposed
__device__ float g_hT   [DFF * BATCH];            // mlp hidden transposed [4096][64]
__device__ float g_part [8 * BATCH * DMODEL];     // split-K partials (max 8x64x1024 / 2x64x3072)
__device__ float g_pattn[BATCH * NHEAD * SPLIT * 68];

// ---------------------------------------------------------------------------
// cp.async helpers
// ---------------------------------------------------------------------------
__device__ __forceinline__ void cp_async16(unsigned int dst, const void* src) {
    asm volatile("cp.async.cg.shared.global [%0], [%1], 16;\n" :: "r"(dst), "l"(src));
}
__device__ __forceinline__ void cp_commit() {
    asm volatile("cp.async.commit_group;\n");
}
template<int N> __device__ __forceinline__ void cp_wait() {
    asm volatile("cp.async.wait_group %0;\n" :: "n"(N));
}

// packed f32x2 helpers
__device__ __forceinline__ void fma2(unsigned long long& d,
                                     unsigned long long a, unsigned long long b) {
    asm("fma.rn.f32x2 %0, %1, %2, %0;" : "+l"(d) : "l"(a), "l"(b));
}
__device__ __forceinline__ unsigned long long dup2(float x) {
    unsigned long long r;
    asm("mov.b64 %0, {%1, %1};" : "=l"(r) : "r"(__float_as_uint(x)));
    return r;
}
__device__ __forceinline__ float2 unpk(unsigned long long v) {
    unsigned int lo, hi;
    asm("mov.b64 {%0, %1}, %2;" : "=r"(lo), "=r"(hi) : "l"(v));
    return make_float2(__uint_as_float(lo), __uint_as_float(hi));
}

// ---------------------------------------------------------------------------
// Pipelined GEMM core: C[64,N] tile (BN=32) from At[K][64] and B[K][N].
// ---------------------------------------------------------------------------
__device__ __forceinline__ void gemm_load_stage(float* gsm, int stg,
        const float* At, const float* B, int N, int k0, int n0, int tid)
{
    float* As = gsm + stg * G_STG_F;
    float* Bs = As + G_A_F;
#pragma unroll
    for (int r = 0; r < 8; r++) {                 // A: 1024 float4
        int idx = r * 128 + tid;
        int kk = idx >> 4, c = idx & 15;
        unsigned int dst = (unsigned int)__cvta_generic_to_shared(As + kk * 64 + c * 4);
        cp_async16(dst, At + (size_t)(k0 + kk) * 64 + c * 4);
    }
#pragma unroll
    for (int r = 0; r < 4; r++) {                 // B: 512 float4
        int idx = r * 128 + tid;
        int kk = idx >> 3, c = idx & 7;
        unsigned int dst = (unsigned int)__cvta_generic_to_shared(Bs + kk * 32 + c * 4);
        cp_async16(dst, B + (size_t)(k0 + kk) * N + n0 + c * 4);
    }
    cp_commit();
}

__device__ __forceinline__ void gemm_compute_stage(const float* gsm, int stg,
        int tx, int ty, unsigned long long acc2[2][4])
{
    const float* As = gsm + stg * G_STG_F;
    const float* Bs = As + G_A_F;
#pragma unroll 16
    for (int kk = 0; kk < 64; kk++) {
        ulonglong2 a2 = *(const ulonglong2*)(As + kk * 64 + ty * 4);
        float4 b4 = *(const float4*)(Bs + kk * 32 + tx * 4);
        unsigned long long bd0 = dup2(b4.x), bd1 = dup2(b4.y),
                           bd2 = dup2(b4.z), bd3 = dup2(b4.w);
        fma2(acc2[0][0], a2.x, bd0); fma2(acc2[0][1], a2.x, bd1);
        fma2(acc2[0][2], a2.x, bd2); fma2(acc2[0][3], a2.x, bd3);
        fma2(acc2[1][0], a2.y, bd0); fma2(acc2[1][1], a2.y, bd1);
        fma2(acc2[1][2], a2.y, bd2); fma2(acc2[1][3], a2.y, bd3);
    }
}

__device__ __forceinline__ void gemm_mainloop(float* gsm,
        const float* At, const float* B, int N, int ks, int iters, int n0,
        int tid, int tx, int ty, unsigned long long acc2[2][4])
{
#pragma unroll
    for (int s = 0; s < G_NST; s++)
        if (s < iters) gemm_load_stage(gsm, s, At, B, N, ks + s * 64, n0, tid);

    for (int i = 0; i < iters; i++) {
        int issued  = (i + G_NST < iters) ? (i + G_NST) : iters;
        int pending = issued - i - 1;
        if (pending >= 2)      cp_wait<2>();
        else if (pending == 1) cp_wait<1>();
        else                   cp_wait<0>();
        __syncthreads();
        gemm_compute_stage(gsm, i % G_NST, tx, ty, acc2);
        __syncthreads();
        if (i + G_NST < iters)
            gemm_load_stage(gsm, i % G_NST, At, B, N, ks + (i + G_NST) * 64, n0, tid);
    }
}

// Split-K partial GEMM: part[sp][64][N] = At[ks:ke][64]^T @ B[ks:ke][N]
__global__ void __launch_bounds__(128)
gemmT_part(const float* __restrict__ At, const float* __restrict__ B,
           float* __restrict__ part, int N, int kchunk)
{
    extern __shared__ float gsm[];
    const int tid = threadIdx.x;
    const int n0  = blockIdx.x * 32;
    const int ks  = blockIdx.y * kchunk;
    const int iters = kchunk >> 6;
    const int tx = tid & 7, ty = tid >> 3;

    unsigned long long acc2[2][4] = {{0ull,0ull,0ull,0ull},{0ull,0ull,0ull,0ull}};
    gemm_mainloop(gsm, At, B, N, ks, iters, n0, tid, tx, ty, acc2);

    float* pout = part + (size_t)blockIdx.y * 64 * N;
#pragma unroll
    for (int i2 = 0; i2 < 2; i2++) {
        float2 v0 = unpk(acc2[i2][0]), v1 = unpk(acc2[i2][1]),
               v2 = unpk(acc2[i2][2]), v3 = unpk(acc2[i2][3]);
        int m = ty * 4 + i2 * 2;
        *(float4*)(pout + (size_t)m * N + n0 + tx * 4) =
            make_float4(v0.x, v1.x, v2.x, v3.x);
        *(float4*)(pout + (size_t)(m + 1) * N + n0 + tx * 4) =
            make_float4(v0.y, v1.y, v2.y, v3.y);
    }
}

// Full GEMM + bias + relu, writes C TRANSPOSED: Ct[N][64]
__global__ void __launch_bounds__(128)
gemmT_relu_t(const float* __restrict__ At, const float* __restrict__ B,
             const float* __restrict__ bias, float* __restrict__ Ct,
             int N, int K)
{
    extern __shared__ float gsm[];
    const int tid = threadIdx.x;
    const int n0  = blockIdx.x * 32;
    const int iters = K >> 6;
    const int tx = tid & 7, ty = tid >> 3;

    unsigned long long acc2[2][4] = {{0ull,0ull,0ull,0ull},{0ull,0ull,0ull,0ull}};
    gemm_mainloop(gsm, At, B, N, 0, iters, n0, tid, tx, ty, acc2);

    float4 bb = *(const float4*)(bias + n0 + tx * 4);
    float bj[4] = {bb.x, bb.y, bb.z, bb.w};
#pragma unroll
    for (int i2 = 0; i2 < 2; i2++) {
        float2 vj[4] = {unpk(acc2[i2][0]), unpk(acc2[i2][1]),
                        unpk(acc2[i2][2]), unpk(acc2[i2][3])};
        int m = ty * 4 + i2 * 2;
#pragma unroll
        for (int j = 0; j < 4; j++) {
            float a = fmaxf(vj[j].x + bj[j], 0.f);
            float c = fmaxf(vj[j].y + bj[j], 0.f);
            Ct[(size_t)(n0 + tx * 4 + j) * 64 + m]     = a;
            Ct[(size_t)(n0 + tx * 4 + j) * 64 + m + 1] = c;
        }
    }
}

// ---------------------------------------------------------------------------
// qkv reduce: out[64][3072] = part0 + part1 + bias
// ---------------------------------------------------------------------------
__global__ void __launch_bounds__(256)
qkv_reduce(const float* __restrict__ part, const float* __restrict__ bias,
           float* __restrict__ out)
{
    int fi = blockIdx.x * 256 + threadIdx.x;     // float4 index [0, 49152)
    int c4 = fi % 768;
    float4 p0 = ((const float4*)part)[fi];
    float4 p1 = ((const float4*)part)[49152 + fi];
    float4 bb = ((const float4*)bias)[c4];
    ((float4*)out)[fi] = make_float4(p0.x + p1.x + bb.x, p0.y + p1.y + bb.y,
                                     p0.z + p1.z + bb.z, p0.w + p1.w + bb.w);
}

// ---------------------------------------------------------------------------
// x transpose: in[64][1024] -> outT[1024][64]
// ---------------------------------------------------------------------------
__global__ void __launch_bounds__(256)
transpose64(const float* __restrict__ in, float* __restrict__ outT)
{
    __shared__ float tile[32][33];
    int c = blockIdx.x * 32 + threadIdx.x;       // col of in
    int r = blockIdx.y * 32;                     // row base of in
#pragma unroll
    for (int j = 0; j < 32; j += 8)
        tile[threadIdx.y + j][threadIdx.x] = in[(size_t)(r + threadIdx.y + j) * 1024 + c];
    __syncthreads();
    int rr = blockIdx.y * 32 + threadIdx.x;      // row of in = col of outT
    int cc = blockIdx.x * 32;                    // col of in = row of outT
#pragma unroll
    for (int j = 0; j < 32; j += 8)
        outT[(size_t)(cc + threadIdx.y + j) * 64 + rr] = tile[threadIdx.x][threadIdx.y + j];
}

// ---------------------------------------------------------------------------
// Fused: sum split-K partials + bias + residual, then LayerNorm.
// DUAL: also write transposed copy outT[1024][64].
// ---------------------------------------------------------------------------
template<int S, bool DUAL>
__global__ void __launch_bounds__(256)
reduce_ln(const float* __restrict__ part, const float* __restrict__ bias,
          const float* __restrict__ res,  const float* __restrict__ w,
          const float* __restrict__ bq,   float* __restrict__ out,
          float* __restrict__ outT)
{
    const int row = blockIdx.x;
    const int tid = threadIdx.x;

    float v[4];
    float s = 0.f, ss = 0.f;
#pragma unroll
    for (int j = 0; j < 4; j++) {
        int col = tid + 256 * j;
        float x = bias[col] + res[(size_t)row * DMODEL + col];
#pragma unroll
        for (int sp = 0; sp < S; sp++)
            x += part[(size_t)sp * (64 * DMODEL) + (size_t)row * DMODEL + col];
        v[j] = x;
        s += x;
        ss += x * x;
    }
#pragma unroll
    for (int off = 16; off > 0; off >>= 1) {
        s  += __shfl_xor_sync(0xffffffffu, s,  off);
        ss += __shfl_xor_sync(0xffffffffu, ss, off);
    }
    __shared__ float rs[8], rss[8];
    int wid = tid >> 5, lane = tid & 31;
    if (lane == 0) { rs[wid] = s; rss[wid] = ss; }
    __syncthreads();
    __shared__ float s_mean, s_inv;
    if (tid == 0) {
        float S1 = 0.f, S2 = 0.f;
#pragma unroll
        for (int i = 0; i < 8; i++) { S1 += rs[i]; S2 += rss[i]; }
        float mean = S1 * (1.f / DMODEL);
        float var  = S2 * (1.f / DMODEL) - mean * mean;
        s_mean = mean;
        s_inv  = rsqrtf(var + LN_EPS);
    }
    __syncthreads();
    float mean = s_mean, inv = s_inv;
#pragma unroll
    for (int j = 0; j < 4; j++) {
        int col = tid + 256 * j;
        float val = (v[j] - mean) * inv * w[col] + bq[col];
        out[(size_t)row * DMODEL + col] = val;
        if (DUAL) outT[(size_t)col * 64 + row] = val;
    }
}

// ---------------------------------------------------------------------------
// Attention v3 (unchanged from R5): split-KV pipelined flash-decode.
// ---------------------------------------------------------------------------
__device__ __forceinline__ void issue_tile64(float* sm, int buf,
                                             const float* kb, const float* vb,
                                             int t0, int tid)
{
    float* kd = sm + buf * STAGE_F;
    float* vd = kd + TILE_F;
    const float4* ks = (const float4*)(kb + (size_t)t0 * HDIM);
    const float4* vs = (const float4*)(vb + (size_t)t0 * HDIM);
#pragma unroll
    for (int it = 0; it < 4; it++) {
        int idx = it * 256 + tid;
        int row = idx >> 4;
        int c   = idx & 15;
        unsigned int dK = (unsigned int)__cvta_generic_to_shared(kd + row * ROWPITCH + c * 4);
        cp_async16(dK, ks + row * 16 + c);
        unsigned int dV = (unsigned int)__cvta_generic_to_shared(vd + row * ROWPITCH + c * 4);
        cp_async16(dV, vs + row * 16 + c);
    }
    cp_commit();
}

__global__ void __launch_bounds__(256, 2)
attn3_kernel(const float* __restrict__ qkv,
             const float* __restrict__ kc,
             const float* __restrict__ vc,
             const int*   __restrict__ kvlen,
             float* __restrict__ part)
{
    extern __shared__ float sm[];
    float* p_arr = sm + OFF_PARR;
    float* q_s   = sm + OFF_QS;
    float* wmax  = sm + OFF_WMAX;
    float* wsum  = sm + OFF_WSUM;
    float* red   = sm + OFF_RED;

    const int bh   = blockIdx.x;
    const int sp   = blockIdx.y;
    const int b    = bh >> 4;
    const int h    = bh & 15;
    const int tid  = threadIdx.x;
    const int lane = tid & 31;
    const int w    = tid >> 5;

    const int len   = kvlen[b];
    const int start = sp * SPLIT_ROWS;
    if (start >= len) return;
    const int end    = (start + SPLIT_ROWS < len) ? (start + SPLIT_ROWS) : len;
    const int ntiles = (end - start + TS - 1) / TS;

    const float SCALE = 0.125f * 1.4426950408889634f;

    const float* qp = qkv + (size_t)b * 3072 + h * HDIM;
    if (tid < HDIM) q_s[tid] = qp[tid] * SCALE;

    const size_t rowbase = ((size_t)(b * NHEAD + h)) * TMAX * HDIM;
    const float* kb = kc + rowbase + (size_t)start * HDIM;
    const float* vb = vc + rowbase + (size_t)start * HDIM;

#pragma unroll
    for (int s = 0; s < NST; s++)
        if (s < ntiles) issue_tile64(sm, s, kb, vb, s * TS, tid);
    __syncthreads();

    const int r  = tid >> 2;
    const int qr = tid & 3;
    float4 qv[4];
#pragma unroll
    for (int j = 0; j < 4; j++)
        qv[j] = *(const float4*)&q_s[qr * 16 + j * 4];

    const int d  = tid & 63;
    const int ch = tid >> 6;

    float m_run = -1e30f, l_run = 0.f, acc = 0.f;

    for (int i = 0; i < ntiles; i++) {
        int issued  = (i + NST < ntiles) ? (i + NST) : ntiles;
        int pending = issued - i - 1;
        if (pending >= 2)      cp_wait<2>();
        else if (pending == 1) cp_wait<1>();
        else                   cp_wait<0>();
        __syncthreads();

        const float* Ks = sm + (i % NST) * STAGE_F;
        const float* Vs = Ks + TILE_F;

        float s = 0.f;
        const float4* kr = (const float4*)&Ks[r * ROWPITCH + qr * 16];
#pragma unroll
        for (int j = 0; j < 4; j++) {
            float4 kf = kr[j];
            s = fmaf(qv[j].x, kf.x,
                fmaf(qv[j].y, kf.y,
                fmaf(qv[j].z, kf.z,
                fmaf(qv[j].w, kf.w, s))));
        }
        s += __shfl_xor_sync(0xffffffffu, s, 1);
        s += __shfl_xor_sync(0xffffffffu, s, 2);

        int t = start + i * TS + r;
        if (t >= end) s = -1e30f;

        float wm = s;
        wm = fmaxf(wm, __shfl_xor_sync(0xffffffffu, wm, 4));
        wm = fmaxf(wm, __shfl_xor_sync(0xffffffffu, wm, 8));
        wm = fmaxf(wm, __shfl_xor_sync(0xffffffffu, wm, 16));
        if (lane == 0) wmax[w] = wm;
        __syncthreads();

        float mt = wmax[0];
#pragma unroll
        for (int k = 1; k < 8; k++) mt = fmaxf(mt, wmax[k]);
        float m_new = fmaxf(m_run, mt);
        float corr  = exp2f(m_run - m_new);

        float p = exp2f(s - m_new);
        if (qr == 0) p_arr[r] = p;
        float ps = p;
        ps += __shfl_xor_sync(0xffffffffu, ps, 4);
        ps += __shfl_xor_sync(0xffffffffu, ps, 8);
        ps += __shfl_xor_sync(0xffffffffu, ps, 16);
        if (lane == 0) wsum[w] = ps;
        __syncthreads();

        float tsum = wsum[0];
#pragma unroll
        for (int k = 1; k < 8; k++) tsum += wsum[k];
        l_run = l_run * corr + tsum;
        m_run = m_new;

        acc *= corr;
        const float* vcol = Vs + ch * 16 * ROWPITCH + d;
        const float* pp   = p_arr + ch * 16;
#pragma unroll
        for (int rr = 0; rr < 16; rr++)
            acc = fmaf(pp[rr], vcol[(size_t)rr * ROWPITCH], acc);
        __syncthreads();

        if (i + NST < ntiles)
            issue_tile64(sm, i % NST, kb, vb, (i + NST) * TS, tid);
    }

    red[tid] = acc;
    __syncthreads();
    if (tid < HDIM) {
        float O = red[tid] + red[64 + tid] + red[128 + tid] + red[192 + tid];
        float* po = part + (size_t)(bh * SPLIT + sp) * 68;
        po[2 + tid] = O;
        if (tid == 0) { po[0] = m_run; po[1] = l_run; }
    }
}

// ---------------------------------------------------------------------------
// Combine split partials + new token -> oT [1024][64] (transposed for GEMM).
// ---------------------------------------------------------------------------
__global__ void __launch_bounds__(64)
attn_combine(const float* __restrict__ qkv, const float* __restrict__ part,
             const int* __restrict__ kvlen, float* __restrict__ oT)
{
    const int bh = blockIdx.x;
    const int b  = bh >> 4;
    const int h  = bh & 15;
    const int d  = threadIdx.x;
    const int len  = kvlen[b];
    const int nact = (len + SPLIT_ROWS - 1) / SPLIT_ROWS;

    const float* qp = qkv + (size_t)b * 3072 + h * HDIM;
    const float* kn = qkv + (size_t)b * 3072 + DMODEL     + h * HDIM;
    const float* vn = qkv + (size_t)b * 3072 + 2 * DMODEL + h * HDIM;

    __shared__ float scr[64];
    __shared__ float snew_sh;
    scr[d] = qp[d] * kn[d];
    __syncthreads();
    if (d < 32) {
        float x = scr[d] + scr[d + 32];
#pragma unroll
        for (int off = 16; off > 0; off >>= 1)
            x += __shfl_xor_sync(0xffffffffu, x, off);
        if (d == 0) snew_sh = x * 0.125f * 1.4426950408889634f;
    }
    __syncthreads();

    float snew = snew_sh;
    float ms[SPLIT], ls[SPLIT];
    float M = snew;
    for (int s = 0; s < nact; s++) {
        const float* po = part + (size_t)(bh * SPLIT + s) * 68;
        ms[s] = po[0];
        ls[s] = po[1];
        M = fmaxf(M, ms[s]);
    }
    float pn = exp2f(snew - M);
    float L  = pn;
    float O  = pn * vn[d];
    for (int s = 0; s < nact; s++) {
        float c = exp2f(ms[s] - M);
        L = fmaf(ls[s], c, L);
        O = fmaf(part[(size_t)(bh * SPLIT + s) * 68 + 2 + d], c, O);
    }
    oT[(size_t)(h * HDIM + d) * 64 + b] = O / L;
}

// ---------------------------------------------------------------------------
// Launch
// ---------------------------------------------------------------------------
extern "C" void kernel_launch(void* const* d_in, const int* in_sizes, int n_in,
                              void* d_out, int out_size)
{
    const float* x       = (const float*)d_in[0];
    const float* k_cache = (const float*)d_in[1];
    const float* v_cache = (const float*)d_in[2];
    const int*   kv_len  = (const int*)  d_in[4];
    const float* qkv_w   = (const float*)d_in[6];
    const float* qkv_b   = (const float*)d_in[7];
    const float* out_w   = (const float*)d_in[8];
    const float* out_b   = (const float*)d_in[9];
    const float* ln1_w   = (const float*)d_in[10];
    const float* ln1_b   = (const float*)d_in[11];
    const float* ln2_w   = (const float*)d_in[12];
    const float* ln2_b   = (const float*)d_in[13];
    const float* mlp_w1  = (const float*)d_in[14];
    const float* mlp_b1  = (const float*)d_in[15];
    const float* mlp_w2  = (const float*)d_in[16];
    const float* mlp_b2  = (const float*)d_in[17];
    float* out = (float*)d_out;

    float *p_xT, *p_qkv, *p_oT, *p_ln1, *p_ln1T, *p_hT, *p_part, *p_pattn;
    cudaGetSymbolAddress((void**)&p_xT,    g_xT);
    cudaGetSymbolAddress((void**)&p_qkv,   g_qkv);
    cudaGetSymbolAddress((void**)&p_oT,    g_oT);
    cudaGetSymbolAddress((void**)&p_ln1,   g_ln1);
    cudaGetSymbolAddress((void**)&p_ln1T,  g_ln1T);
    cudaGetSymbolAddress((void**)&p_hT,    g_hT);
    cudaGetSymbolAddress((void**)&p_part,  g_part);
    cudaGetSymbolAddress((void**)&p_pattn, g_pattn);

    cudaFuncSetAttribute(attn3_kernel,
                         cudaFuncAttributeMaxDynamicSharedMemorySize, SMEM_BYTES);
    cudaFuncSetAttribute(gemmT_part,
                         cudaFuncAttributeMaxDynamicSharedMemorySize, G_SMEM_BYTES);
    cudaFuncSetAttribute(gemmT_relu_t,
                         cudaFuncAttributeMaxDynamicSharedMemorySize, G_SMEM_BYTES);

    // 1. transpose x -> xT [1024][64]
    transpose64<<<dim3(32, 2), dim3(32, 8)>>>(x, p_xT);

    // 2. QKV projection, split-K=2: part = xT^T @ qkv_w
    gemmT_part<<<dim3(96, 2), 128, G_SMEM_BYTES>>>(p_xT, qkv_w, p_part, 3072, 512);

    // 3. qkv = part0 + part1 + bias
    qkv_reduce<<<192, 256>>>(p_part, qkv_b, p_qkv);

    // 4. Attention decode, split-KV x4 -> partials
    attn3_kernel<<<dim3(BATCH * NHEAD, SPLIT), 256, SMEM_BYTES>>>(
        p_qkv, k_cache, v_cache, kv_len, p_pattn);

    // 5. Combine partials + new token -> oT
    attn_combine<<<BATCH * NHEAD, 64>>>(p_qkv, p_pattn, kv_len, p_oT);

    // 6. Output projection, split-K=4
    gemmT_part<<<dim3(32, 4), 128, G_SMEM_BYTES>>>(p_oT, out_w, p_part, 1024, 256);

    // 7. reduce + bias + residual(x) + LN1 -> ln1 (+ ln1T)
    reduce_ln<4, true><<<BATCH, 256>>>(p_part, out_b, x, ln1_w, ln1_b,
                                       p_ln1, p_ln1T);

    // 8. MLP up + ReLU -> hT (transposed)
    gemmT_relu_t<<<128, 128, G_SMEM_BYTES>>>(p_ln1T, mlp_w1, mlp_b1, p_hT,
                                             4096, 1024);

    // 9. MLP down, split-K=8
    gemmT_part<<<dim3(32, 8), 128, G_SMEM_BYTES>>>(p_hT, mlp_w2, p_part, 1024, 512);

    // 10. reduce + bias + residual(ln1) + LN2 -> out
    reduce_ln<8, false><<<BATCH, 256>>>(p_part, mlp_b2, p_ln1, ln2_w, ln2_b,
                                        out, nullptr);
}

// round 8
// speedup vs baseline: 2.5073x; 1.0466x over previous
#include <cuda_runtime.h>
#include <cuda_bf16.h>
#include <cstdint>
#include <math.h>

// ---------------------------------------------------------------------------
// Problem constants
// ---------------------------------------------------------------------------
#define BATCH 64
#define DMODEL 1024
#define NHEAD 16
#define HDIM 64
#define TMAX 2048
#define DFF 4096
#define LN_EPS 1e-5f

// Attention tiling: NST=2 -> 71KB smem -> 3 CTAs/SM
#define TS 64
#define NST 2
#define ROWPITCH 68
#define TILE_F (TS * ROWPITCH)
#define STAGE_F (2 * TILE_F)
#define SPLIT 4
#define SPLIT_ROWS 512

#define OFF_PARR (NST * STAGE_F)
#define OFF_QS   (OFF_PARR + TS)
#define OFF_WMAX (OFF_QS + 64)
#define OFF_WSUM (OFF_WMAX + 8)
#define OFF_RED  (OFF_WSUM + 8)
#define SMEM_F   (OFF_RED + 256)
#define SMEM_BYTES (SMEM_F * 4)          // ~71 KB

// GEMM tiling: BM=64, BN=32, BK=64, 3-stage cp.async pipeline
#define G_A_F   4096
#define G_B_F   2048
#define G_STG_F 6144
#define G_NST   3
#define G_SMEM_BYTES (G_NST * G_STG_F * 4)

#define QKV_PART_OFF (64 * 3072)         // offset of split-1 partial for QKV
#define MLP_PART_OFF (64 * 4096)         // offset of split-1 partial for MLP1

// ---------------------------------------------------------------------------
// Scratch (device globals; no allocation allowed)
// ---------------------------------------------------------------------------
__device__ float g_xT   [DMODEL * BATCH];
__device__ float g_oT   [DMODEL * BATCH];
__device__ float g_ln1  [BATCH * DMODEL];
__device__ float g_ln1T [DMODEL * BATCH];
__device__ float g_hT   [DFF * BATCH];
__device__ float g_part [8 * BATCH * DMODEL];     // 512K floats, reused per stage
__device__ float g_pattn[BATCH * NHEAD * SPLIT * 68];

// ---------------------------------------------------------------------------
// cp.async helpers
// ---------------------------------------------------------------------------
__device__ __forceinline__ void cp_async16(unsigned int dst, const void* src) {
    asm volatile("cp.async.cg.shared.global [%0], [%1], 16;\n" :: "r"(dst), "l"(src));
}
__device__ __forceinline__ void cp_commit() {
    asm volatile("cp.async.commit_group;\n");
}
template<int N> __device__ __forceinline__ void cp_wait() {
    asm volatile("cp.async.wait_group %0;\n" :: "n"(N));
}

// packed f32x2 helpers
__device__ __forceinline__ void fma2(unsigned long long& d,
                                     unsigned long long a, unsigned long long b) {
    asm("fma.rn.f32x2 %0, %1, %2, %0;" : "+l"(d) : "l"(a), "l"(b));
}
__device__ __forceinline__ unsigned long long dup2(float x) {
    unsigned long long r;
    asm("mov.b64 %0, {%1, %1};" : "=l"(r) : "r"(__float_as_uint(x)));
    return r;
}
__device__ __forceinline__ float2 unpk(unsigned long long v) {
    unsigned int lo, hi;
    asm("mov.b64 {%0, %1}, %2;" : "=r"(lo), "=r"(hi) : "l"(v));
    return make_float2(__uint_as_float(lo), __uint_as_float(hi));
}

// qkv value reconstructed from the two QKV split-K partials + bias
__device__ __forceinline__ float qkv_val(const float* part, const float* bias,
                                         int b, int col) {
    size_t idx = (size_t)b * 3072 + col;
    return part[idx] + part[QKV_PART_OFF + idx] + bias[col];
}

// ---------------------------------------------------------------------------
// Pipelined GEMM core: C[64,N] tile (BN=32) from At[K][64] and B[K][N].
// ---------------------------------------------------------------------------
__device__ __forceinline__ void gemm_load_stage(float* gsm, int stg,
        const float* At, const float* B, int N, int k0, int n0, int tid)
{
    float* As = gsm + stg * G_STG_F;
    float* Bs = As + G_A_F;
#pragma unroll
    for (int r = 0; r < 8; r++) {
        int idx = r * 128 + tid;
        int kk = idx >> 4, c = idx & 15;
        unsigned int dst = (unsigned int)__cvta_generic_to_shared(As + kk * 64 + c * 4);
        cp_async16(dst, At + (size_t)(k0 + kk) * 64 + c * 4);
    }
#pragma unroll
    for (int r = 0; r < 4; r++) {
        int idx = r * 128 + tid;
        int kk = idx >> 3, c = idx & 7;
        unsigned int dst = (unsigned int)__cvta_generic_to_shared(Bs + kk * 32 + c * 4);
        cp_async16(dst, B + (size_t)(k0 + kk) * N + n0 + c * 4);
    }
    cp_commit();
}

__device__ __forceinline__ void gemm_compute_stage(const float* gsm, int stg,
        int tx, int ty, unsigned long long acc2[2][4])
{
    const float* As = gsm + stg * G_STG_F;
    const float* Bs = As + G_A_F;
#pragma unroll 16
    for (int kk = 0; kk < 64; kk++) {
        ulonglong2 a2 = *(const ulonglong2*)(As + kk * 64 + ty * 4);
        float4 b4 = *(const float4*)(Bs + kk * 32 + tx * 4);
        unsigned long long bd0 = dup2(b4.x), bd1 = dup2(b4.y),
                           bd2 = dup2(b4.z), bd3 = dup2(b4.w);
        fma2(acc2[0][0], a2.x, bd0); fma2(acc2[0][1], a2.x, bd1);
        fma2(acc2[0][2], a2.x, bd2); fma2(acc2[0][3], a2.x, bd3);
        fma2(acc2[1][0], a2.y, bd0); fma2(acc2[1][1], a2.y, bd1);
        fma2(acc2[1][2], a2.y, bd2); fma2(acc2[1][3], a2.y, bd3);
    }
}

__device__ __forceinline__ void gemm_mainloop(float* gsm,
        const float* At, const float* B, int N, int ks, int iters, int n0,
        int tid, int tx, int ty, unsigned long long acc2[2][4])
{
#pragma unroll
    for (int s = 0; s < G_NST; s++)
        if (s < iters) gemm_load_stage(gsm, s, At, B, N, ks + s * 64, n0, tid);

    for (int i = 0; i < iters; i++) {
        int issued  = (i + G_NST < iters) ? (i + G_NST) : iters;
        int pending = issued - i - 1;
        if (pending >= 2)      cp_wait<2>();
        else if (pending == 1) cp_wait<1>();
        else                   cp_wait<0>();
        __syncthreads();
        gemm_compute_stage(gsm, i % G_NST, tx, ty, acc2);
        __syncthreads();
        if (i + G_NST < iters)
            gemm_load_stage(gsm, i % G_NST, At, B, N, ks + (i + G_NST) * 64, n0, tid);
    }
}

// Split-K partial GEMM: part[sp][64][N] = At[ks:ke][64]^T @ B[ks:ke][N]
__global__ void __launch_bounds__(128)
gemmT_part(const float* __restrict__ At, const float* __restrict__ B,
           float* __restrict__ part, int N, int kchunk)
{
    extern __shared__ float gsm[];
    const int tid = threadIdx.x;
    const int n0  = blockIdx.x * 32;
    const int ks  = blockIdx.y * kchunk;
    const int iters = kchunk >> 6;
    const int tx = tid & 7, ty = tid >> 3;

    unsigned long long acc2[2][4] = {{0ull,0ull,0ull,0ull},{0ull,0ull,0ull,0ull}};
    gemm_mainloop(gsm, At, B, N, ks, iters, n0, tid, tx, ty, acc2);

    float* pout = part + (size_t)blockIdx.y * 64 * N;
#pragma unroll
    for (int i2 = 0; i2 < 2; i2++) {
        float2 v0 = unpk(acc2[i2][0]), v1 = unpk(acc2[i2][1]),
               v2 = unpk(acc2[i2][2]), v3 = unpk(acc2[i2][3]);
        int m = ty * 4 + i2 * 2;
        *(float4*)(pout + (size_t)m * N + n0 + tx * 4) =
            make_float4(v0.x, v1.x, v2.x, v3.x);
        *(float4*)(pout + (size_t)(m + 1) * N + n0 + tx * 4) =
            make_float4(v0.y, v1.y, v2.y, v3.y);
    }
}

// ---------------------------------------------------------------------------
// x transpose: in[64][1024] -> outT[1024][64]
// ---------------------------------------------------------------------------
__global__ void __launch_bounds__(256)
transpose64(const float* __restrict__ in, float* __restrict__ outT)
{
    __shared__ float tile[32][33];
    int c = blockIdx.x * 32 + threadIdx.x;
    int r = blockIdx.y * 32;
#pragma unroll
    for (int j = 0; j < 32; j += 8)
        tile[threadIdx.y + j][threadIdx.x] = in[(size_t)(r + threadIdx.y + j) * 1024 + c];
    __syncthreads();
    int rr = blockIdx.y * 32 + threadIdx.x;
    int cc = blockIdx.x * 32;
#pragma unroll
    for (int j = 0; j < 32; j += 8)
        outT[(size_t)(cc + threadIdx.y + j) * 64 + rr] = tile[threadIdx.x][threadIdx.y + j];
}

// ---------------------------------------------------------------------------
// MLP1 epilogue: hT[4096][64] = relu(part0 + part1 + bias), transposed.
// grid (128, 2), block (32, 8)
// ---------------------------------------------------------------------------
__global__ void __launch_bounds__(256)
relu_reduce_t(const float* __restrict__ part, const float* __restrict__ bias,
              float* __restrict__ outT)
{
    __shared__ float tile[32][33];
    int c = blockIdx.x * 32 + threadIdx.x;       // n (DFF)
    int r = blockIdx.y * 32;                     // m (batch)
    float bq = bias[c];
#pragma unroll
    for (int j = 0; j < 32; j += 8) {
        size_t idx = (size_t)(r + threadIdx.y + j) * DFF + c;
        float v = part[idx] + part[MLP_PART_OFF + idx] + bq;
        tile[threadIdx.y + j][threadIdx.x] = fmaxf(v, 0.f);
    }
    __syncthreads();
    int rr = blockIdx.y * 32 + threadIdx.x;      // m
    int cc = blockIdx.x * 32;                    // n
#pragma unroll
    for (int j = 0; j < 32; j += 8)
        outT[(size_t)(cc + threadIdx.y + j) * 64 + rr] = tile[threadIdx.x][threadIdx.y + j];
}

// ---------------------------------------------------------------------------
// Fused: sum split-K partials + bias + residual, then LayerNorm.
// ---------------------------------------------------------------------------
template<int S, bool DUAL>
__global__ void __launch_bounds__(256)
reduce_ln(const float* __restrict__ part, const float* __restrict__ bias,
          const float* __restrict__ res,  const float* __restrict__ w,
          const float* __restrict__ bq,   float* __restrict__ out,
          float* __restrict__ outT)
{
    const int row = blockIdx.x;
    const int tid = threadIdx.x;

    float v[4];
    float s = 0.f, ss = 0.f;
#pragma unroll
    for (int j = 0; j < 4; j++) {
        int col = tid + 256 * j;
        float x = bias[col] + res[(size_t)row * DMODEL + col];
#pragma unroll
        for (int sp = 0; sp < S; sp++)
            x += part[(size_t)sp * (64 * DMODEL) + (size_t)row * DMODEL + col];
        v[j] = x;
        s += x;
        ss += x * x;
    }
#pragma unroll
    for (int off = 16; off > 0; off >>= 1) {
        s  += __shfl_xor_sync(0xffffffffu, s,  off);
        ss += __shfl_xor_sync(0xffffffffu, ss, off);
    }
    __shared__ float rs[8], rss[8];
    int wid = tid >> 5, lane = tid & 31;
    if (lane == 0) { rs[wid] = s; rss[wid] = ss; }
    __syncthreads();
    __shared__ float s_mean, s_inv;
    if (tid == 0) {
        float S1 = 0.f, S2 = 0.f;
#pragma unroll
        for (int i = 0; i < 8; i++) { S1 += rs[i]; S2 += rss[i]; }
        float mean = S1 * (1.f / DMODEL);
        float var  = S2 * (1.f / DMODEL) - mean * mean;
        s_mean = mean;
        s_inv  = rsqrtf(var + LN_EPS);
    }
    __syncthreads();
    float mean = s_mean, inv = s_inv;
#pragma unroll
    for (int j = 0; j < 4; j++) {
        int col = tid + 256 * j;
        float val = (v[j] - mean) * inv * w[col] + bq[col];
        out[(size_t)row * DMODEL + col] = val;
        if (DUAL) outT[(size_t)col * 64 + row] = val;
    }
}

// ---------------------------------------------------------------------------
// Attention: split-KV pipelined flash-decode, NST=2, 3 CTAs/SM.
// q reconstructed from QKV split-K partials + bias (no qkv_reduce kernel).
// ---------------------------------------------------------------------------
__device__ __forceinline__ void issue_tile64(float* sm, int buf,
                                             const float* kb, const float* vb,
                                             int t0, int tid)
{
    float* kd = sm + buf * STAGE_F;
    float* vd = kd + TILE_F;
    const float4* ks = (const float4*)(kb + (size_t)t0 * HDIM);
    const float4* vs = (const float4*)(vb + (size_t)t0 * HDIM);
#pragma unroll
    for (int it = 0; it < 4; it++) {
        int idx = it * 256 + tid;
        int row = idx >> 4;
        int c   = idx & 15;
        unsigned int dK = (unsigned int)__cvta_generic_to_shared(kd + row * ROWPITCH + c * 4);
        cp_async16(dK, ks + row * 16 + c);
        unsigned int dV = (unsigned int)__cvta_generic_to_shared(vd + row * ROWPITCH + c * 4);
        cp_async16(dV, vs + row * 16 + c);
    }
    cp_commit();
}

__global__ void __launch_bounds__(256, 3)
attn3_kernel(const float* __restrict__ qpart,
             const float* __restrict__ qbias,
             const float* __restrict__ kc,
             const float* __restrict__ vc,
             const int*   __restrict__ kvlen,
             float* __restrict__ part)
{
    extern __shared__ float sm[];
    float* p_arr = sm + OFF_PARR;
    float* q_s   = sm + OFF_QS;
    float* wmax  = sm + OFF_WMAX;
    float* wsum  = sm + OFF_WSUM;
    float* red   = sm + OFF_RED;

    const int bh   = blockIdx.x;
    const int sp   = blockIdx.y;
    const int b    = bh >> 4;
    const int h    = bh & 15;
    const int tid  = threadIdx.x;
    const int lane = tid & 31;
    const int w    = tid >> 5;

    const int len   = kvlen[b];
    const int start = sp * SPLIT_ROWS;
    if (start >= len) return;
    const int end    = (start + SPLIT_ROWS < len) ? (start + SPLIT_ROWS) : len;
    const int ntiles = (end - start + TS - 1) / TS;

    const float SCALE = 0.125f * 1.4426950408889634f;

    if (tid < HDIM)
        q_s[tid] = qkv_val(qpart, qbias, b, h * HDIM + tid) * SCALE;

    const size_t rowbase = ((size_t)(b * NHEAD + h)) * TMAX * HDIM;
    const float* kb = kc + rowbase + (size_t)start * HDIM;
    const float* vb = vc + rowbase + (size_t)start * HDIM;

#pragma unroll
    for (int s = 0; s < NST; s++)
        if (s < ntiles) issue_tile64(sm, s, kb, vb, s * TS, tid);
    __syncthreads();

    const int r  = tid >> 2;
    const int qr = tid & 3;
    float4 qv[4];
#pragma unroll
    for (int j = 0; j < 4; j++)
        qv[j] = *(const float4*)&q_s[qr * 16 + j * 4];

    const int d  = tid & 63;
    const int ch = tid >> 6;

    float m_run = -1e30f, l_run = 0.f, acc = 0.f;

    for (int i = 0; i < ntiles; i++) {
        int issued  = (i + NST < ntiles) ? (i + NST) : ntiles;
        int pending = issued - i - 1;
        if (pending >= 1) cp_wait<1>();
        else              cp_wait<0>();
        __syncthreads();

        const float* Ks = sm + (i % NST) * STAGE_F;
        const float* Vs = Ks + TILE_F;

        float s = 0.f;
        const float4* kr = (const float4*)&Ks[r * ROWPITCH + qr * 16];
#pragma unroll
        for (int j = 0; j < 4; j++) {
            float4 kf = kr[j];
            s = fmaf(qv[j].x, kf.x,
                fmaf(qv[j].y, kf.y,
                fmaf(qv[j].z, kf.z,
                fmaf(qv[j].w, kf.w, s))));
        }
        s += __shfl_xor_sync(0xffffffffu, s, 1);
        s += __shfl_xor_sync(0xffffffffu, s, 2);

        int t = start + i * TS + r;
        if (t >= end) s = -1e30f;

        float wm = s;
        wm = fmaxf(wm, __shfl_xor_sync(0xffffffffu, wm, 4));
        wm = fmaxf(wm, __shfl_xor_sync(0xffffffffu, wm, 8));
        wm = fmaxf(wm, __shfl_xor_sync(0xffffffffu, wm, 16));
        if (lane == 0) wmax[w] = wm;
        __syncthreads();

        float mt = wmax[0];
#pragma unroll
        for (int k = 1; k < 8; k++) mt = fmaxf(mt, wmax[k]);
        float m_new = fmaxf(m_run, mt);
        float corr  = exp2f(m_run - m_new);

        float p = exp2f(s - m_new);
        if (qr == 0) p_arr[r] = p;
        float ps = p;
        ps += __shfl_xor_sync(0xffffffffu, ps, 4);
        ps += __shfl_xor_sync(0xffffffffu, ps, 8);
        ps += __shfl_xor_sync(0xffffffffu, ps, 16);
        if (lane == 0) wsum[w] = ps;
        __syncthreads();

        float tsum = wsum[0];
#pragma unroll
        for (int k = 1; k < 8; k++) tsum += wsum[k];
        l_run = l_run * corr + tsum;
        m_run = m_new;

        acc *= corr;
        const float* vcol = Vs + ch * 16 * ROWPITCH + d;
        const float* pp   = p_arr + ch * 16;
#pragma unroll
        for (int rr = 0; rr < 16; rr++)
            acc = fmaf(pp[rr], vcol[(size_t)rr * ROWPITCH], acc);
        __syncthreads();

        if (i + NST < ntiles)
            issue_tile64(sm, i % NST, kb, vb, (i + NST) * TS, tid);
    }

    red[tid] = acc;
    __syncthreads();
    if (tid < HDIM) {
        float O = red[tid] + red[64 + tid] + red[128 + tid] + red[192 + tid];
        float* po = part + (size_t)(bh * SPLIT + sp) * 68;
        po[2 + tid] = O;
        if (tid == 0) { po[0] = m_run; po[1] = l_run; }
    }
}

// ---------------------------------------------------------------------------
// Combine split partials + new token -> oT [1024][64].
// ---------------------------------------------------------------------------
__global__ void __launch_bounds__(64)
attn_combine(const float* __restrict__ qpart, const float* __restrict__ qbias,
             const float* __restrict__ part,
             const int* __restrict__ kvlen, float* __restrict__ oT)
{
    const int bh = blockIdx.x;
    const int b  = bh >> 4;
    const int h  = bh & 15;
    const int d  = threadIdx.x;
    const int len  = kvlen[b];
    const int nact = (len + SPLIT_ROWS - 1) / SPLIT_ROWS;

    float qd = qkv_val(qpart, qbias, b, h * HDIM + d);
    float knd = qkv_val(qpart, qbias, b, DMODEL + h * HDIM + d);
    float vnd = qkv_val(qpart, qbias, b, 2 * DMODEL + h * HDIM + d);

    __shared__ float scr[64];
    __shared__ float snew_sh;
    scr[d] = qd * knd;
    __syncthreads();
    if (d < 32) {
        float x = scr[d] + scr[d + 32];
#pragma unroll
        for (int off = 16; off > 0; off >>= 1)
            x += __shfl_xor_sync(0xffffffffu, x, off);
        if (d == 0) snew_sh = x * 0.125f * 1.4426950408889634f;
    }
    __syncthreads();

    float snew = snew_sh;
    float ms[SPLIT], ls[SPLIT];
    float M = snew;
    for (int s = 0; s < nact; s++) {
        const float* po = part + (size_t)(bh * SPLIT + s) * 68;
        ms[s] = po[0];
        ls[s] = po[1];
        M = fmaxf(M, ms[s]);
    }
    float pn = exp2f(snew - M);
    float L  = pn;
    float O  = pn * vnd;
    for (int s = 0; s < nact; s++) {
        float c = exp2f(ms[s] - M);
        L = fmaf(ls[s], c, L);
        O = fmaf(part[(size_t)(bh * SPLIT + s) * 68 + 2 + d], c, O);
    }
    oT[(size_t)(h * HDIM + d) * 64 + b] = O / L;
}

// ---------------------------------------------------------------------------
// Launch
// ---------------------------------------------------------------------------
extern "C" void kernel_launch(void* const* d_in, const int* in_sizes, int n_in,
                              void* d_out, int out_size)
{
    const float* x       = (const float*)d_in[0];
    const float* k_cache = (const float*)d_in[1];
    const float* v_cache = (const float*)d_in[2];
    const int*   kv_len  = (const int*)  d_in[4];
    const float* qkv_w   = (const float*)d_in[6];
    const float* qkv_b   = (const float*)d_in[7];
    const float* out_w   = (const float*)d_in[8];
    const float* out_b   = (const float*)d_in[9];
    const float* ln1_w   = (const float*)d_in[10];
    const float* ln1_b   = (const float*)d_in[11];
    const float* ln2_w   = (const float*)d_in[12];
    const float* ln2_b   = (const float*)d_in[13];
    const float* mlp_w1  = (const float*)d_in[14];
    const float* mlp_b1  = (const float*)d_in[15];
    const float* mlp_w2  = (const float*)d_in[16];
    const float* mlp_b2  = (const float*)d_in[17];
    float* out = (float*)d_out;

    float *p_xT, *p_oT, *p_ln1, *p_ln1T, *p_hT, *p_part, *p_pattn;
    cudaGetSymbolAddress((void**)&p_xT,    g_xT);
    cudaGetSymbolAddress((void**)&p_oT,    g_oT);
    cudaGetSymbolAddress((void**)&p_ln1,   g_ln1);
    cudaGetSymbolAddress((void**)&p_ln1T,  g_ln1T);
    cudaGetSymbolAddress((void**)&p_hT,    g_hT);
    cudaGetSymbolAddress((void**)&p_part,  g_part);
    cudaGetSymbolAddress((void**)&p_pattn, g_pattn);

    cudaFuncSetAttribute(attn3_kernel,
                         cudaFuncAttributeMaxDynamicSharedMemorySize, SMEM_BYTES);
    cudaFuncSetAttribute(gemmT_part,
                         cudaFuncAttributeMaxDynamicSharedMemorySize, G_SMEM_BYTES);

    // 1. transpose x -> xT [1024][64]
    transpose64<<<dim3(32, 2), dim3(32, 8)>>>(x, p_xT);

    // 2. QKV projection, split-K=2 -> part[0..1][64][3072]
    gemmT_part<<<dim3(96, 2), 128, G_SMEM_BYTES>>>(p_xT, qkv_w, p_part, 3072, 512);

    // 3. Attention decode, split-KV x4 (reads QKV partials directly)
    attn3_kernel<<<dim3(BATCH * NHEAD, SPLIT), 256, SMEM_BYTES>>>(
        p_part, qkv_b, k_cache, v_cache, kv_len, p_pattn);

    // 4. Combine partials + new token -> oT
    attn_combine<<<BATCH * NHEAD, 64>>>(p_part, qkv_b, p_pattn, kv_len, p_oT);

    // 5. Output projection, split-K=4 -> part[0..3][64][1024]
    gemmT_part<<<dim3(32, 4), 128, G_SMEM_BYTES>>>(p_oT, out_w, p_part, 1024, 256);

    // 6. reduce + bias + residual(x) + LN1 -> ln1 (+ ln1T)
    reduce_ln<4, true><<<BATCH, 256>>>(p_part, out_b, x, ln1_w, ln1_b,
                                       p_ln1, p_ln1T);

    // 7. MLP up, split-K=2 -> part[0..1][64][4096]
    gemmT_part<<<dim3(128, 2), 128, G_SMEM_BYTES>>>(p_ln1T, mlp_w1, p_part, 4096, 512);

    // 8. hT = relu(part0 + part1 + bias), transposed
    relu_reduce_t<<<dim3(128, 2), dim3(32, 8)>>>(p_part, mlp_b1, p_hT);

    // 9. MLP down, split-K=8 -> part[0..7][64][1024]
    gemmT_part<<<dim3(32, 8), 128, G_SMEM_BYTES>>>(p_hT, mlp_w2, p_part, 1024, 512);

    // 10. reduce + bias + residual(ln1) + LN2 -> out
    reduce_ln<8, false><<<BATCH, 256>>>(p_part, mlp_b2, p_ln1, ln2_w, ln2_b,
                                        out, nullptr);
}

// round 9
// speedup vs baseline: 2.8143x; 1.1225x over previous
#include <cuda_runtime.h>
#include <cuda_bf16.h>
#include <cstdint>
#include <math.h>

// ---------------------------------------------------------------------------
// Problem constants
// ---------------------------------------------------------------------------
#define BATCH 64
#define DMODEL 1024
#define NHEAD 16
#define HDIM 64
#define TMAX 2048
#define DFF 4096
#define LN_EPS 1e-5f

// Attention tiling: NST=2 -> 71KB smem -> 3 CTAs/SM
#define TS 64
#define NST 2
#define ROWPITCH 68
#define TILE_F (TS * ROWPITCH)
#define STAGE_F (2 * TILE_F)
#define SPLIT 4
#define SPLIT_ROWS 512

#define OFF_PARR (NST * STAGE_F)
#define OFF_QS   (OFF_PARR + TS)
#define OFF_WMAX (OFF_QS + 64)
#define OFF_WSUM (OFF_WMAX + 8)
#define OFF_RED  (OFF_WSUM + 8)
#define SMEM_F   (OFF_RED + 256)
#define SMEM_BYTES (SMEM_F * 4)          // ~71 KB

// GEMM tiling: BM=64, BN=32, BK=64, 3-stage cp.async pipeline, tf32 MMA
#define GA_PITCH 72                      // conflict-free A fragment loads
#define GB_PITCH 40                      // conflict-free B fragment loads
#define G_A_F   (64 * GA_PITCH)          // 4608
#define G_B_F   (64 * GB_PITCH)          // 2560
#define G_STG_F (G_A_F + G_B_F)          // 7168
#define G_NST   3
#define G_SMEM_BYTES (G_NST * G_STG_F * 4)   // 86016

#define QKV_PART_OFF (64 * 3072)
#define MLP_PART_OFF (64 * 4096)

// ---------------------------------------------------------------------------
// Scratch (device globals; no allocation allowed)
// ---------------------------------------------------------------------------
__device__ float g_xT   [DMODEL * BATCH];
__device__ float g_oT   [DMODEL * BATCH];
__device__ float g_ln1  [BATCH * DMODEL];
__device__ float g_ln1T [DMODEL * BATCH];
__device__ float g_hT   [DFF * BATCH];
__device__ float g_part [8 * BATCH * DMODEL];
__device__ float g_pattn[BATCH * NHEAD * SPLIT * 68];

// ---------------------------------------------------------------------------
// cp.async helpers
// ---------------------------------------------------------------------------
__device__ __forceinline__ void cp_async16(unsigned int dst, const void* src) {
    asm volatile("cp.async.cg.shared.global [%0], [%1], 16;\n" :: "r"(dst), "l"(src));
}
__device__ __forceinline__ void cp_commit() {
    asm volatile("cp.async.commit_group;\n");
}
template<int N> __device__ __forceinline__ void cp_wait() {
    asm volatile("cp.async.wait_group %0;\n" :: "n"(N));
}

// tf32 helpers
__device__ __forceinline__ unsigned int f2tf32(float x) {
    unsigned int r;
    asm("cvt.rna.tf32.f32 %0, %1;" : "=r"(r) : "f"(x));
    return r;
}
__device__ __forceinline__ void mma_tf32(float d[4],
        unsigned int a0, unsigned int a1, unsigned int a2, unsigned int a3,
        unsigned int b0, unsigned int b1)
{
    asm volatile(
        "mma.sync.aligned.m16n8k8.row.col.f32.tf32.tf32.f32 "
        "{%0,%1,%2,%3}, {%4,%5,%6,%7}, {%8,%9}, {%0,%1,%2,%3};"
        : "+f"(d[0]), "+f"(d[1]), "+f"(d[2]), "+f"(d[3])
        : "r"(a0), "r"(a1), "r"(a2), "r"(a3), "r"(b0), "r"(b1));
}

// qkv value reconstructed from the two QKV split-K partials + bias
__device__ __forceinline__ float qkv_val(const float* part, const float* bias,
                                         int b, int col) {
    size_t idx = (size_t)b * 3072 + col;
    return part[idx] + part[QKV_PART_OFF + idx] + bias[col];
}

// ---------------------------------------------------------------------------
// Pipelined tf32 GEMM: C[64,N] tile (BN=32) from At[K][64] and B[K][N].
// As[k][m] pitch 72, Bs[k][n] pitch 40.
// ---------------------------------------------------------------------------
__device__ __forceinline__ void gemm_load_stage(float* gsm, int stg,
        const float* At, const float* B, int N, int k0, int n0, int tid)
{
    float* As = gsm + stg * G_STG_F;
    float* Bs = As + G_A_F;
#pragma unroll
    for (int r = 0; r < 8; r++) {                 // A: 1024 float4
        int idx = r * 128 + tid;
        int kk = idx >> 4, c = idx & 15;
        unsigned int dst = (unsigned int)__cvta_generic_to_shared(As + kk * GA_PITCH + c * 4);
        cp_async16(dst, At + (size_t)(k0 + kk) * 64 + c * 4);
    }
#pragma unroll
    for (int r = 0; r < 4; r++) {                 // B: 512 float4
        int idx = r * 128 + tid;
        int kk = idx >> 3, c = idx & 7;
        unsigned int dst = (unsigned int)__cvta_generic_to_shared(Bs + kk * GB_PITCH + c * 4);
        cp_async16(dst, B + (size_t)(k0 + kk) * N + n0 + c * 4);
    }
    cp_commit();
}

// warp w computes rows [w*16, w*16+16), 4 n-tiles of 8. acc[nt][4].
__device__ __forceinline__ void gemm_compute_stage(const float* gsm, int stg,
        int w, int g, int tg, float acc[4][4])
{
    const float* As = gsm + stg * G_STG_F;
    const float* Bs = As + G_A_F;
#pragma unroll
    for (int kc = 0; kc < 8; kc++) {
        int kb = kc * 8 + tg;
        const float* Ab = As + kb * GA_PITCH + w * 16 + g;
        unsigned int a0 = f2tf32(Ab[0]);
        unsigned int a1 = f2tf32(Ab[8]);
        unsigned int a2 = f2tf32(Ab[4 * GA_PITCH]);
        unsigned int a3 = f2tf32(Ab[4 * GA_PITCH + 8]);
        const float* Bb = Bs + kb * GB_PITCH + g;
#pragma unroll
        for (int nt = 0; nt < 4; nt++) {
            unsigned int b0 = f2tf32(Bb[nt * 8]);
            unsigned int b1 = f2tf32(Bb[4 * GB_PITCH + nt * 8]);
            mma_tf32(acc[nt], a0, a1, a2, a3, b0, b1);
        }
    }
}

__device__ __forceinline__ void gemm_mainloop(float* gsm,
        const float* At, const float* B, int N, int ks, int iters, int n0,
        int tid, int w, int g, int tg, float acc[4][4])
{
#pragma unroll
    for (int s = 0; s < G_NST; s++)
        if (s < iters) gemm_load_stage(gsm, s, At, B, N, ks + s * 64, n0, tid);

    for (int i = 0; i < iters; i++) {
        int issued  = (i + G_NST < iters) ? (i + G_NST) : iters;
        int pending = issued - i - 1;
        if (pending >= 2)      cp_wait<2>();
        else if (pending == 1) cp_wait<1>();
        else                   cp_wait<0>();
        __syncthreads();
        gemm_compute_stage(gsm, i % G_NST, w, g, tg, acc);
        __syncthreads();
        if (i + G_NST < iters)
            gemm_load_stage(gsm, i % G_NST, At, B, N, ks + (i + G_NST) * 64, n0, tid);
    }
}

// Split-K partial GEMM: part[sp][64][N] = At[ks:ke][64]^T @ B[ks:ke][N]
__global__ void __launch_bounds__(128)
gemmT_part(const float* __restrict__ At, const float* __restrict__ B,
           float* __restrict__ part, int N, int kchunk)
{
    extern __shared__ float gsm[];
    const int tid = threadIdx.x;
    const int n0  = blockIdx.x * 32;
    const int ks  = blockIdx.y * kchunk;
    const int iters = kchunk >> 6;
    const int lane = tid & 31, w = tid >> 5;
    const int g = lane >> 2, tg = lane & 3;

    float acc[4][4];
#pragma unroll
    for (int i = 0; i < 4; i++)
#pragma unroll
        for (int j = 0; j < 4; j++) acc[i][j] = 0.f;

    gemm_mainloop(gsm, At, B, N, ks, iters, n0, tid, w, g, tg, acc);

    float* pout = part + (size_t)blockIdx.y * 64 * N;
    int m0 = w * 16 + g;
    int m1 = m0 + 8;
#pragma unroll
    for (int nt = 0; nt < 4; nt++) {
        int col = n0 + nt * 8 + tg * 2;
        *(float2*)(pout + (size_t)m0 * N + col) = make_float2(acc[nt][0], acc[nt][1]);
        *(float2*)(pout + (size_t)m1 * N + col) = make_float2(acc[nt][2], acc[nt][3]);
    }
}

// ---------------------------------------------------------------------------
// x transpose: in[64][1024] -> outT[1024][64]
// ---------------------------------------------------------------------------
__global__ void __launch_bounds__(256)
transpose64(const float* __restrict__ in, float* __restrict__ outT)
{
    __shared__ float tile[32][33];
    int c = blockIdx.x * 32 + threadIdx.x;
    int r = blockIdx.y * 32;
#pragma unroll
    for (int j = 0; j < 32; j += 8)
        tile[threadIdx.y + j][threadIdx.x] = in[(size_t)(r + threadIdx.y + j) * 1024 + c];
    __syncthreads();
    int rr = blockIdx.y * 32 + threadIdx.x;
    int cc = blockIdx.x * 32;
#pragma unroll
    for (int j = 0; j < 32; j += 8)
        outT[(size_t)(cc + threadIdx.y + j) * 64 + rr] = tile[threadIdx.x][threadIdx.y + j];
}

// ---------------------------------------------------------------------------
// MLP1 epilogue: hT[4096][64] = relu(part0 + part1 + bias), transposed.
// ---------------------------------------------------------------------------
__global__ void __launch_bounds__(256)
relu_reduce_t(const float* __restrict__ part, const float* __restrict__ bias,
              float* __restrict__ outT)
{
    __shared__ float tile[32][33];
    int c = blockIdx.x * 32 + threadIdx.x;
    int r = blockIdx.y * 32;
    float bq = bias[c];
#pragma unroll
    for (int j = 0; j < 32; j += 8) {
        size_t idx = (size_t)(r + threadIdx.y + j) * DFF + c;
        float v = part[idx] + part[MLP_PART_OFF + idx] + bq;
        tile[threadIdx.y + j][threadIdx.x] = fmaxf(v, 0.f);
    }
    __syncthreads();
    int rr = blockIdx.y * 32 + threadIdx.x;
    int cc = blockIdx.x * 32;
#pragma unroll
    for (int j = 0; j < 32; j += 8)
        outT[(size_t)(cc + threadIdx.y + j) * 64 + rr] = tile[threadIdx.x][threadIdx.y + j];
}

// ---------------------------------------------------------------------------
// Fused: sum split-K partials + bias + residual, then LayerNorm.
// ---------------------------------------------------------------------------
template<int S, bool DUAL>
__global__ void __launch_bounds__(256)
reduce_ln(const float* __restrict__ part, const float* __restrict__ bias,
          const float* __restrict__ res,  const float* __restrict__ w,
          const float* __restrict__ bq,   float* __restrict__ out,
          float* __restrict__ outT)
{
    const int row = blockIdx.x;
    const int tid = threadIdx.x;

    float v[4];
    float s = 0.f, ss = 0.f;
#pragma unroll
    for (int j = 0; j < 4; j++) {
        int col = tid + 256 * j;
        float x = bias[col] + res[(size_t)row * DMODEL + col];
#pragma unroll
        for (int sp = 0; sp < S; sp++)
            x += part[(size_t)sp * (64 * DMODEL) + (size_t)row * DMODEL + col];
        v[j] = x;
        s += x;
        ss += x * x;
    }
#pragma unroll
    for (int off = 16; off > 0; off >>= 1) {
        s  += __shfl_xor_sync(0xffffffffu, s,  off);
        ss += __shfl_xor_sync(0xffffffffu, ss, off);
    }
    __shared__ float rs[8], rss[8];
    int wid = tid >> 5, lane = tid & 31;
    if (lane == 0) { rs[wid] = s; rss[wid] = ss; }
    __syncthreads();
    __shared__ float s_mean, s_inv;
    if (tid == 0) {
        float S1 = 0.f, S2 = 0.f;
#pragma unroll
        for (int i = 0; i < 8; i++) { S1 += rs[i]; S2 += rss[i]; }
        float mean = S1 * (1.f / DMODEL);
        float var  = S2 * (1.f / DMODEL) - mean * mean;
        s_mean = mean;
        s_inv  = rsqrtf(var + LN_EPS);
    }
    __syncthreads();
    float mean = s_mean, inv = s_inv;
#pragma unroll
    for (int j = 0; j < 4; j++) {
        int col = tid + 256 * j;
        float val = (v[j] - mean) * inv * w[col] + bq[col];
        out[(size_t)row * DMODEL + col] = val;
        if (DUAL) outT[(size_t)col * 64 + row] = val;
    }
}

// ---------------------------------------------------------------------------
// Attention: split-KV pipelined flash-decode (unchanged from R8).
// ---------------------------------------------------------------------------
__device__ __forceinline__ void issue_tile64(float* sm, int buf,
                                             const float* kb, const float* vb,
                                             int t0, int tid)
{
    float* kd = sm + buf * STAGE_F;
    float* vd = kd + TILE_F;
    const float4* ks = (const float4*)(kb + (size_t)t0 * HDIM);
    const float4* vs = (const float4*)(vb + (size_t)t0 * HDIM);
#pragma unroll
    for (int it = 0; it < 4; it++) {
        int idx = it * 256 + tid;
        int row = idx >> 4;
        int c   = idx & 15;
        unsigned int dK = (unsigned int)__cvta_generic_to_shared(kd + row * ROWPITCH + c * 4);
        cp_async16(dK, ks + row * 16 + c);
        unsigned int dV = (unsigned int)__cvta_generic_to_shared(vd + row * ROWPITCH + c * 4);
        cp_async16(dV, vs + row * 16 + c);
    }
    cp_commit();
}

__global__ void __launch_bounds__(256, 3)
attn3_kernel(const float* __restrict__ qpart,
             const float* __restrict__ qbias,
             const float* __restrict__ kc,
             const float* __restrict__ vc,
             const int*   __restrict__ kvlen,
             float* __restrict__ part)
{
    extern __shared__ float sm[];
    float* p_arr = sm + OFF_PARR;
    float* q_s   = sm + OFF_QS;
    float* wmax  = sm + OFF_WMAX;
    float* wsum  = sm + OFF_WSUM;
    float* red   = sm + OFF_RED;

    const int bh   = blockIdx.x;
    const int sp   = blockIdx.y;
    const int b    = bh >> 4;
    const int h    = bh & 15;
    const int tid  = threadIdx.x;
    const int lane = tid & 31;
    const int w    = tid >> 5;

    const int len   = kvlen[b];
    const int start = sp * SPLIT_ROWS;
    if (start >= len) return;
    const int end    = (start + SPLIT_ROWS < len) ? (start + SPLIT_ROWS) : len;
    const int ntiles = (end - start + TS - 1) / TS;

    const float SCALE = 0.125f * 1.4426950408889634f;

    if (tid < HDIM)
        q_s[tid] = qkv_val(qpart, qbias, b, h * HDIM + tid) * SCALE;

    const size_t rowbase = ((size_t)(b * NHEAD + h)) * TMAX * HDIM;
    const float* kb = kc + rowbase + (size_t)start * HDIM;
    const float* vb = vc + rowbase + (size_t)start * HDIM;

#pragma unroll
    for (int s = 0; s < NST; s++)
        if (s < ntiles) issue_tile64(sm, s, kb, vb, s * TS, tid);
    __syncthreads();

    const int r  = tid >> 2;
    const int qr = tid & 3;
    float4 qv[4];
#pragma unroll
    for (int j = 0; j < 4; j++)
        qv[j] = *(const float4*)&q_s[qr * 16 + j * 4];

    const int d  = tid & 63;
    const int ch = tid >> 6;

    float m_run = -1e30f, l_run = 0.f, acc = 0.f;

    for (int i = 0; i < ntiles; i++) {
        int issued  = (i + NST < ntiles) ? (i + NST) : ntiles;
        int pending = issued - i - 1;
        if (pending >= 1) cp_wait<1>();
        else              cp_wait<0>();
        __syncthreads();

        const float* Ks = sm + (i % NST) * STAGE_F;
        const float* Vs = Ks + TILE_F;

        float s = 0.f;
        const float4* kr = (const float4*)&Ks[r * ROWPITCH + qr * 16];
#pragma unroll
        for (int j = 0; j < 4; j++) {
            float4 kf = kr[j];
            s = fmaf(qv[j].x, kf.x,
                fmaf(qv[j].y, kf.y,
                fmaf(qv[j].z, kf.z,
                fmaf(qv[j].w, kf.w, s))));
        }
        s += __shfl_xor_sync(0xffffffffu, s, 1);
        s += __shfl_xor_sync(0xffffffffu, s, 2);

        int t = start + i * TS + r;
        if (t >= end) s = -1e30f;

        float wm = s;
        wm = fmaxf(wm, __shfl_xor_sync(0xffffffffu, wm, 4));
        wm = fmaxf(wm, __shfl_xor_sync(0xffffffffu, wm, 8));
        wm = fmaxf(wm, __shfl_xor_sync(0xffffffffu, wm, 16));
        if (lane == 0) wmax[w] = wm;
        __syncthreads();

        float mt = wmax[0];
#pragma unroll
        for (int k = 1; k < 8; k++) mt = fmaxf(mt, wmax[k]);
        float m_new = fmaxf(m_run, mt);
        float corr  = exp2f(m_run - m_new);

        float p = exp2f(s - m_new);
        if (qr == 0) p_arr[r] = p;
        float ps = p;
        ps += __shfl_xor_sync(0xffffffffu, ps, 4);
        ps += __shfl_xor_sync(0xffffffffu, ps, 8);
        ps += __shfl_xor_sync(0xffffffffu, ps, 16);
        if (lane == 0) wsum[w] = ps;
        __syncthreads();

        float tsum = wsum[0];
#pragma unroll
        for (int k = 1; k < 8; k++) tsum += wsum[k];
        l_run = l_run * corr + tsum;
        m_run = m_new;

        acc *= corr;
        const float* vcol = Vs + ch * 16 * ROWPITCH + d;
        const float* pp   = p_arr + ch * 16;
#pragma unroll
        for (int rr = 0; rr < 16; rr++)
            acc = fmaf(pp[rr], vcol[(size_t)rr * ROWPITCH], acc);
        __syncthreads();

        if (i + NST < ntiles)
            issue_tile64(sm, i % NST, kb, vb, (i + NST) * TS, tid);
    }

    red[tid] = acc;
    __syncthreads();
    if (tid < HDIM) {
        float O = red[tid] + red[64 + tid] + red[128 + tid] + red[192 + tid];
        float* po = part + (size_t)(bh * SPLIT + sp) * 68;
        po[2 + tid] = O;
        if (tid == 0) { po[0] = m_run; po[1] = l_run; }
    }
}

// ---------------------------------------------------------------------------
// Combine: 4 (b,h) groups per 256-thread block. grid = 256.
// ---------------------------------------------------------------------------
__global__ void __launch_bounds__(256)
attn_combine(const float* __restrict__ qpart, const float* __restrict__ qbias,
             const float* __restrict__ part,
             const int* __restrict__ kvlen, float* __restrict__ oT)
{
    const int sub = threadIdx.x >> 6;            // group 0..3
    const int d   = threadIdx.x & 63;
    const int bh  = blockIdx.x * 4 + sub;
    const int b   = bh >> 4;
    const int h   = bh & 15;
    const int len  = kvlen[b];
    const int nact = (len + SPLIT_ROWS - 1) / SPLIT_ROWS;

    float qd  = qkv_val(qpart, qbias, b, h * HDIM + d);
    float knd = qkv_val(qpart, qbias, b, DMODEL + h * HDIM + d);
    float vnd = qkv_val(qpart, qbias, b, 2 * DMODEL + h * HDIM + d);

    __shared__ float scr[4][64];
    __shared__ float snew_sh[4];
    scr[sub][d] = qd * knd;
    __syncthreads();
    if (d < 32) {                                // first warp of each group
        float x = scr[sub][d] + scr[sub][d + 32];
#pragma unroll
        for (int off = 16; off > 0; off >>= 1)
            x += __shfl_xor_sync(0xffffffffu, x, off);
        if (d == 0) snew_sh[sub] = x * 0.125f * 1.4426950408889634f;
    }
    __syncthreads();

    float snew = snew_sh[sub];
    float ms[SPLIT], ls[SPLIT];
    float M = snew;
    for (int s = 0; s < nact; s++) {
        const float* po = part + (size_t)(bh * SPLIT + s) * 68;
        ms[s] = po[0];
        ls[s] = po[1];
        M = fmaxf(M, ms[s]);
    }
    float pn = exp2f(snew - M);
    float L  = pn;
    float O  = pn * vnd;
    for (int s = 0; s < nact; s++) {
        float c = exp2f(ms[s] - M);
        L = fmaf(ls[s], c, L);
        O = fmaf(part[(size_t)(bh * SPLIT + s) * 68 + 2 + d], c, O);
    }
    oT[(size_t)(h * HDIM + d) * 64 + b] = O / L;
}

// ---------------------------------------------------------------------------
// Launch
// ---------------------------------------------------------------------------
extern "C" void kernel_launch(void* const* d_in, const int* in_sizes, int n_in,
                              void* d_out, int out_size)
{
    const float* x       = (const float*)d_in[0];
    const float* k_cache = (const float*)d_in[1];
    const float* v_cache = (const float*)d_in[2];
    const int*   kv_len  = (const int*)  d_in[4];
    const float* qkv_w   = (const float*)d_in[6];
    const float* qkv_b   = (const float*)d_in[7];
    const float* out_w   = (const float*)d_in[8];
    const float* out_b   = (const float*)d_in[9];
    const float* ln1_w   = (const float*)d_in[10];
    const float* ln1_b   = (const float*)d_in[11];
    const float* ln2_w   = (const float*)d_in[12];
    const float* ln2_b   = (const float*)d_in[13];
    const float* mlp_w1  = (const float*)d_in[14];
    const float* mlp_b1  = (const float*)d_in[15];
    const float* mlp_w2  = (const float*)d_in[16];
    const float* mlp_b2  = (const float*)d_in[17];
    float* out = (float*)d_out;

    float *p_xT, *p_oT, *p_ln1, *p_ln1T, *p_hT, *p_part, *p_pattn;
    cudaGetSymbolAddress((void**)&p_xT,    g_xT);
    cudaGetSymbolAddress((void**)&p_oT,    g_oT);
    cudaGetSymbolAddress((void**)&p_ln1,   g_ln1);
    cudaGetSymbolAddress((void**)&p_ln1T,  g_ln1T);
    cudaGetSymbolAddress((void**)&p_hT,    g_hT);
    cudaGetSymbolAddress((void**)&p_part,  g_part);
    cudaGetSymbolAddress((void**)&p_pattn, g_pattn);

    cudaFuncSetAttribute(attn3_kernel,
                         cudaFuncAttributeMaxDynamicSharedMemorySize, SMEM_BYTES);
    cudaFuncSetAttribute(gemmT_part,
                         cudaFuncAttributeMaxDynamicSharedMemorySize, G_SMEM_BYTES);

    // 1. transpose x -> xT [1024][64]
    transpose64<<<dim3(32, 2), dim3(32, 8)>>>(x, p_xT);

    // 2. QKV projection, split-K=2 -> part[0..1][64][3072]
    gemmT_part<<<dim3(96, 2), 128, G_SMEM_BYTES>>>(p_xT, qkv_w, p_part, 3072, 512);

    // 3. Attention decode, split-KV x4 (reads QKV partials directly)
    attn3_kernel<<<dim3(BATCH * NHEAD, SPLIT), 256, SMEM_BYTES>>>(
        p_part, qkv_b, k_cache, v_cache, kv_len, p_pattn);

    // 4. Combine partials + new token -> oT (4 heads per block)
    attn_combine<<<BATCH * NHEAD / 4, 256>>>(p_part, qkv_b, p_pattn, kv_len, p_oT);

    // 5. Output projection, split-K=4 -> part[0..3][64][1024]
    gemmT_part<<<dim3(32, 4), 128, G_SMEM_BYTES>>>(p_oT, out_w, p_part, 1024, 256);

    // 6. reduce + bias + residual(x) + LN1 -> ln1 (+ ln1T)
    reduce_ln<4, true><<<BATCH, 256>>>(p_part, out_b, x, ln1_w, ln1_b,
                                       p_ln1, p_ln1T);

    // 7. MLP up, split-K=2 -> part[0..1][64][4096]
    gemmT_part<<<dim3(128, 2), 128, G_SMEM_BYTES>>>(p_ln1T, mlp_w1, p_part, 4096, 512);

    // 8. hT = relu(part0 + part1 + bias), transposed
    relu_reduce_t<<<dim3(128, 2), dim3(32, 8)>>>(p_part, mlp_b1, p_hT);

    // 9. MLP down, split-K=8 -> part[0..7][64][1024]
    gemmT_part<<<dim3(32, 8), 128, G_SMEM_BYTES>>>(p_hT, mlp_w2, p_part, 1024, 512);

    // 10. reduce + bias + residual(ln1) + LN2 -> out
    reduce_ln<8, false><<<BATCH, 256>>>(p_part, mlp_b2, p_ln1, ln2_w, ln2_b,
                                        out, nullptr);
}

// round 10
// speedup vs baseline: 2.9675x; 1.0544x over previous
#include <cuda_runtime.h>
#include <cuda_bf16.h>
#include <cstdint>
#include <math.h>

// ---------------------------------------------------------------------------
// Problem constants
// ---------------------------------------------------------------------------
#define BATCH 64
#define DMODEL 1024
#define NHEAD 16
#define HDIM 64
#define TMAX 2048
#define DFF 4096
#define LN_EPS 1e-5f

// Attention tiling: warp-synchronous, NST=2, 72KB smem -> 3 CTAs/SM
#define TS 64
#define NST 2
#define ROWPITCH 68
#define TILE_F (TS * ROWPITCH)
#define STAGE_F (2 * TILE_F)
#define SPLIT 4
#define SPLIT_ROWS 512

#define OFF_QS   (NST * STAGE_F)         // q scaled [64]
#define OFF_RED  (OFF_QS + 64)           // 8 warps * 66 floats
#define SMEM_F   (OFF_RED + 8 * 66)
#define SMEM_BYTES (SMEM_F * 4)          // 72000 B -> 3 CTAs/SM

// GEMM tiling: BM=64, BN=32, BK=64, 3-stage cp.async pipeline, tf32 MMA
#define GA_PITCH 72
#define GB_PITCH 40
#define G_A_F   (64 * GA_PITCH)
#define G_B_F   (64 * GB_PITCH)
#define G_STG_F (G_A_F + G_B_F)
#define G_NST   3
#define G_SMEM_BYTES (G_NST * G_STG_F * 4)

#define QKV_PART_OFF (64 * 3072)
#define MLP_PART_OFF (64 * 4096)

// ---------------------------------------------------------------------------
// Scratch (device globals; no allocation allowed)
// ---------------------------------------------------------------------------
__device__ float g_xT   [DMODEL * BATCH];
__device__ float g_oT   [DMODEL * BATCH];
__device__ float g_ln1  [BATCH * DMODEL];
__device__ float g_ln1T [DMODEL * BATCH];
__device__ float g_hT   [DFF * BATCH];
__device__ float g_part [8 * BATCH * DMODEL];
__device__ float g_pattn[BATCH * NHEAD * SPLIT * 68];

// ---------------------------------------------------------------------------
// cp.async helpers
// ---------------------------------------------------------------------------
__device__ __forceinline__ void cp_async16(unsigned int dst, const void* src) {
    asm volatile("cp.async.cg.shared.global [%0], [%1], 16;\n" :: "r"(dst), "l"(src));
}
__device__ __forceinline__ void cp_commit() {
    asm volatile("cp.async.commit_group;\n");
}
template<int N> __device__ __forceinline__ void cp_wait() {
    asm volatile("cp.async.wait_group %0;\n" :: "n"(N));
}

// tf32 helpers
__device__ __forceinline__ unsigned int f2tf32(float x) {
    unsigned int r;
    asm("cvt.rna.tf32.f32 %0, %1;" : "=r"(r) : "f"(x));
    return r;
}
__device__ __forceinline__ void mma_tf32(float d[4],
        unsigned int a0, unsigned int a1, unsigned int a2, unsigned int a3,
        unsigned int b0, unsigned int b1)
{
    asm volatile(
        "mma.sync.aligned.m16n8k8.row.col.f32.tf32.tf32.f32 "
        "{%0,%1,%2,%3}, {%4,%5,%6,%7}, {%8,%9}, {%0,%1,%2,%3};"
        : "+f"(d[0]), "+f"(d[1]), "+f"(d[2]), "+f"(d[3])
        : "r"(a0), "r"(a1), "r"(a2), "r"(a3), "r"(b0), "r"(b1));
}

// qkv value reconstructed from the two QKV split-K partials + bias
__device__ __forceinline__ float qkv_val(const float* part, const float* bias,
                                         int b, int col) {
    size_t idx = (size_t)b * 3072 + col;
    return part[idx] + part[QKV_PART_OFF + idx] + bias[col];
}

// ---------------------------------------------------------------------------
// Pipelined tf32 GEMM (unchanged from R9)
// ---------------------------------------------------------------------------
__device__ __forceinline__ void gemm_load_stage(float* gsm, int stg,
        const float* At, const float* B, int N, int k0, int n0, int tid)
{
    float* As = gsm + stg * G_STG_F;
    float* Bs = As + G_A_F;
#pragma unroll
    for (int r = 0; r < 8; r++) {
        int idx = r * 128 + tid;
        int kk = idx >> 4, c = idx & 15;
        unsigned int dst = (unsigned int)__cvta_generic_to_shared(As + kk * GA_PITCH + c * 4);
        cp_async16(dst, At + (size_t)(k0 + kk) * 64 + c * 4);
    }
#pragma unroll
    for (int r = 0; r < 4; r++) {
        int idx = r * 128 + tid;
        int kk = idx >> 3, c = idx & 7;
        unsigned int dst = (unsigned int)__cvta_generic_to_shared(Bs + kk * GB_PITCH + c * 4);
        cp_async16(dst, B + (size_t)(k0 + kk) * N + n0 + c * 4);
    }
    cp_commit();
}

__device__ __forceinline__ void gemm_compute_stage(const float* gsm, int stg,
        int w, int g, int tg, float acc[4][4])
{
    const float* As = gsm + stg * G_STG_F;
    const float* Bs = As + G_A_F;
#pragma unroll
    for (int kc = 0; kc < 8; kc++) {
        int kb = kc * 8 + tg;
        const float* Ab = As + kb * GA_PITCH + w * 16 + g;
        unsigned int a0 = f2tf32(Ab[0]);
        unsigned int a1 = f2tf32(Ab[8]);
        unsigned int a2 = f2tf32(Ab[4 * GA_PITCH]);
        unsigned int a3 = f2tf32(Ab[4 * GA_PITCH + 8]);
        const float* Bb = Bs + kb * GB_PITCH + g;
#pragma unroll
        for (int nt = 0; nt < 4; nt++) {
            unsigned int b0 = f2tf32(Bb[nt * 8]);
            unsigned int b1 = f2tf32(Bb[4 * GB_PITCH + nt * 8]);
            mma_tf32(acc[nt], a0, a1, a2, a3, b0, b1);
        }
    }
}

__device__ __forceinline__ void gemm_mainloop(float* gsm,
        const float* At, const float* B, int N, int ks, int iters, int n0,
        int tid, int w, int g, int tg, float acc[4][4])
{
#pragma unroll
    for (int s = 0; s < G_NST; s++)
        if (s < iters) gemm_load_stage(gsm, s, At, B, N, ks + s * 64, n0, tid);

    for (int i = 0; i < iters; i++) {
        int issued  = (i + G_NST < iters) ? (i + G_NST) : iters;
        int pending = issued - i - 1;
        if (pending >= 2)      cp_wait<2>();
        else if (pending == 1) cp_wait<1>();
        else                   cp_wait<0>();
        __syncthreads();
        gemm_compute_stage(gsm, i % G_NST, w, g, tg, acc);
        __syncthreads();
        if (i + G_NST < iters)
            gemm_load_stage(gsm, i % G_NST, At, B, N, ks + (i + G_NST) * 64, n0, tid);
    }
}

__global__ void __launch_bounds__(128)
gemmT_part(const float* __restrict__ At, const float* __restrict__ B,
           float* __restrict__ part, int N, int kchunk)
{
    extern __shared__ float gsm[];
    const int tid = threadIdx.x;
    const int n0  = blockIdx.x * 32;
    const int ks  = blockIdx.y * kchunk;
    const int iters = kchunk >> 6;
    const int lane = tid & 31, w = tid >> 5;
    const int g = lane >> 2, tg = lane & 3;

    float acc[4][4];
#pragma unroll
    for (int i = 0; i < 4; i++)
#pragma unroll
        for (int j = 0; j < 4; j++) acc[i][j] = 0.f;

    gemm_mainloop(gsm, At, B, N, ks, iters, n0, tid, w, g, tg, acc);

    float* pout = part + (size_t)blockIdx.y * 64 * N;
    int m0 = w * 16 + g;
    int m1 = m0 + 8;
#pragma unroll
    for (int nt = 0; nt < 4; nt++) {
        int col = n0 + nt * 8 + tg * 2;
        *(float2*)(pout + (size_t)m0 * N + col) = make_float2(acc[nt][0], acc[nt][1]);
        *(float2*)(pout + (size_t)m1 * N + col) = make_float2(acc[nt][2], acc[nt][3]);
    }
}

// ---------------------------------------------------------------------------
// x transpose: in[64][1024] -> outT[1024][64]
// ---------------------------------------------------------------------------
__global__ void __launch_bounds__(256)
transpose64(const float* __restrict__ in, float* __restrict__ outT)
{
    __shared__ float tile[32][33];
    int c = blockIdx.x * 32 + threadIdx.x;
    int r = blockIdx.y * 32;
#pragma unroll
    for (int j = 0; j < 32; j += 8)
        tile[threadIdx.y + j][threadIdx.x] = in[(size_t)(r + threadIdx.y + j) * 1024 + c];
    __syncthreads();
    int rr = blockIdx.y * 32 + threadIdx.x;
    int cc = blockIdx.x * 32;
#pragma unroll
    for (int j = 0; j < 32; j += 8)
        outT[(size_t)(cc + threadIdx.y + j) * 64 + rr] = tile[threadIdx.x][threadIdx.y + j];
}

// ---------------------------------------------------------------------------
// MLP1 epilogue: hT[4096][64] = relu(part0 + part1 + bias), transposed.
// ---------------------------------------------------------------------------
__global__ void __launch_bounds__(256)
relu_reduce_t(const float* __restrict__ part, const float* __restrict__ bias,
              float* __restrict__ outT)
{
    __shared__ float tile[32][33];
    int c = blockIdx.x * 32 + threadIdx.x;
    int r = blockIdx.y * 32;
    float bq = bias[c];
#pragma unroll
    for (int j = 0; j < 32; j += 8) {
        size_t idx = (size_t)(r + threadIdx.y + j) * DFF + c;
        float v = part[idx] + part[MLP_PART_OFF + idx] + bq;
        tile[threadIdx.y + j][threadIdx.x] = fmaxf(v, 0.f);
    }
    __syncthreads();
    int rr = blockIdx.y * 32 + threadIdx.x;
    int cc = blockIdx.x * 32;
#pragma unroll
    for (int j = 0; j < 32; j += 8)
        outT[(size_t)(cc + threadIdx.y + j) * 64 + rr] = tile[threadIdx.x][threadIdx.y + j];
}

// ---------------------------------------------------------------------------
// Fused: sum split-K partials + bias + residual, then LayerNorm.
// ---------------------------------------------------------------------------
template<int S, bool DUAL>
__global__ void __launch_bounds__(256)
reduce_ln(const float* __restrict__ part, const float* __restrict__ bias,
          const float* __restrict__ res,  const float* __restrict__ w,
          const float* __restrict__ bq,   float* __restrict__ out,
          float* __restrict__ outT)
{
    const int row = blockIdx.x;
    const int tid = threadIdx.x;

    float v[4];
    float s = 0.f, ss = 0.f;
#pragma unroll
    for (int j = 0; j < 4; j++) {
        int col = tid + 256 * j;
        float x = bias[col] + res[(size_t)row * DMODEL + col];
#pragma unroll
        for (int sp = 0; sp < S; sp++)
            x += part[(size_t)sp * (64 * DMODEL) + (size_t)row * DMODEL + col];
        v[j] = x;
        s += x;
        ss += x * x;
    }
#pragma unroll
    for (int off = 16; off > 0; off >>= 1) {
        s  += __shfl_xor_sync(0xffffffffu, s,  off);
        ss += __shfl_xor_sync(0xffffffffu, ss, off);
    }
    __shared__ float rs[8], rss[8];
    int wid = tid >> 5, lane = tid & 31;
    if (lane == 0) { rs[wid] = s; rss[wid] = ss; }
    __syncthreads();
    __shared__ float s_mean, s_inv;
    if (tid == 0) {
        float S1 = 0.f, S2 = 0.f;
#pragma unroll
        for (int i = 0; i < 8; i++) { S1 += rs[i]; S2 += rss[i]; }
        float mean = S1 * (1.f / DMODEL);
        float var  = S2 * (1.f / DMODEL) - mean * mean;
        s_mean = mean;
        s_inv  = rsqrtf(var + LN_EPS);
    }
    __syncthreads();
    float mean = s_mean, inv = s_inv;
#pragma unroll
    for (int j = 0; j < 4; j++) {
        int col = tid + 256 * j;
        float val = (v[j] - mean) * inv * w[col] + bq[col];
        out[(size_t)row * DMODEL + col] = val;
        if (DUAL) outT[(size_t)col * 64 + row] = val;
    }
}

// ---------------------------------------------------------------------------
// Attention v4: WARP-SYNCHRONOUS split-KV flash-decode.
// Warp w exclusively owns rows [w*8, w*8+8) of every tile: it loads them,
// scores them, and keeps a private online softmax + 64-dim V accumulator.
// Zero __syncthreads in the mainloop. One merge at the end.
// ---------------------------------------------------------------------------
__global__ void __launch_bounds__(256, 3)
attn4_kernel(const float* __restrict__ qpart,
             const float* __restrict__ qbias,
             const float* __restrict__ kc,
             const float* __restrict__ vc,
             const int*   __restrict__ kvlen,
             float* __restrict__ part)
{
    extern __shared__ float sm[];
    float* q_s = sm + OFF_QS;
    float* red = sm + OFF_RED;           // 8 warps * 66 floats: m, l, acc[64]

    const int bh   = blockIdx.x;
    const int sp   = blockIdx.y;
    const int b    = bh >> 4;
    const int h    = bh & 15;
    const int tid  = threadIdx.x;
    const int lane = tid & 31;
    const int w    = tid >> 5;

    const int len   = kvlen[b];
    const int start = sp * SPLIT_ROWS;
    if (start >= len) return;
    const int end    = (start + SPLIT_ROWS < len) ? (start + SPLIT_ROWS) : len;
    const int ntiles = (end - start + TS - 1) / TS;

    const float SCALE = 0.125f * 1.4426950408889634f;

    if (tid < HDIM)
        q_s[tid] = qkv_val(qpart, qbias, b, h * HDIM + tid) * SCALE;

    const size_t rowbase = ((size_t)(b * NHEAD + h)) * TMAX * HDIM;
    // warp-private source base: rows w*8.. of each tile
    const float4* kb4 = (const float4*)(kc + rowbase + (size_t)(start + w * 8) * HDIM);
    const float4* vb4 = (const float4*)(vc + rowbase + (size_t)(start + w * 8) * HDIM);
    // warp-private smem slices
    float* kd_base = sm + (size_t)(w * 8) * ROWPITCH;

    // issue this warp's 8 K rows + 8 V rows of tile t (tile index within split)
    auto issue = [&](int buf, int t) {
        float* kd = kd_base + buf * STAGE_F;
        float* vd = kd + TILE_F;
        const float4* ks = kb4 + (size_t)t * TS * 16;   // 16 float4 per row
        const float4* vs = vb4 + (size_t)t * TS * 16;
#pragma unroll
        for (int it = 0; it < 4; it++) {
            int idx = it * 32 + lane;          // [0,128)
            int row = idx >> 4;                // 0..7
            int c   = idx & 15;
            unsigned int dK = (unsigned int)__cvta_generic_to_shared(
                kd + row * ROWPITCH + c * 4);
            cp_async16(dK, ks + row * 16 + c);
            unsigned int dV = (unsigned int)__cvta_generic_to_shared(
                vd + row * ROWPITCH + c * 4);
            cp_async16(dV, vs + row * 16 + c);
        }
        cp_commit();
    };

#pragma unroll
    for (int s = 0; s < NST; s++)
        if (s < ntiles) issue(s, s);
    __syncthreads();   // q_s visible (also covers nothing else)

    // quad layout: 4 lanes per row, 16 dims each
    const int row_local = lane >> 2;     // 0..7
    const int sublane   = lane & 3;
    float4 qv[4];
#pragma unroll
    for (int j = 0; j < 4; j++)
        qv[j] = *(const float4*)&q_s[sublane * 16 + j * 4];

    float m_w = -1e30f, l_w = 0.f;
    float2 acc = make_float2(0.f, 0.f);

    for (int i = 0; i < ntiles; i++) {
        int issued  = (i + NST < ntiles) ? (i + NST) : ntiles;
        int pending = issued - i - 1;
        if (pending >= 1) cp_wait<1>();
        else              cp_wait<0>();
        // NO __syncthreads: this warp only reads rows it loaded itself.

        const float* Ks = kd_base + (i % NST) * STAGE_F;
        const float* Vs = Ks + TILE_F;

        // score for row w*8 + row_local
        float s = 0.f;
        const float4* kr = (const float4*)&Ks[row_local * ROWPITCH + sublane * 16];
#pragma unroll
        for (int j = 0; j < 4; j++) {
            float4 kf = kr[j];
            s = fmaf(qv[j].x, kf.x,
                fmaf(qv[j].y, kf.y,
                fmaf(qv[j].z, kf.z,
                fmaf(qv[j].w, kf.w, s))));
        }
        s += __shfl_xor_sync(0xffffffffu, s, 1);
        s += __shfl_xor_sync(0xffffffffu, s, 2);

        int t = start + i * TS + w * 8 + row_local;
        if (t >= end) s = -1e30f;

        // warp max over its 8 rows
        float wm = s;
        wm = fmaxf(wm, __shfl_xor_sync(0xffffffffu, wm, 4));
        wm = fmaxf(wm, __shfl_xor_sync(0xffffffffu, wm, 8));
        wm = fmaxf(wm, __shfl_xor_sync(0xffffffffu, wm, 16));

        float m_new = fmaxf(m_w, wm);
        float corr  = exp2f(m_w - m_new);
        float p     = exp2f(s - m_new);

        // sum of p over 8 distinct rows (p duplicated within each quad)
        float ps = p;
        ps += __shfl_xor_sync(0xffffffffu, ps, 4);
        ps += __shfl_xor_sync(0xffffffffu, ps, 8);
        ps += __shfl_xor_sync(0xffffffffu, ps, 16);

        l_w = l_w * corr + ps;
        m_w = m_new;

        // V accumulation: lane owns dims (lane*2, lane*2+1)
        acc.x *= corr;
        acc.y *= corr;
        const float* vbase = Vs + lane * 2;
#pragma unroll
        for (int j = 0; j < 8; j++) {
            float pj = __shfl_sync(0xffffffffu, p, j * 4);
            float2 vv = *(const float2*)(vbase + j * ROWPITCH);
            acc.x = fmaf(pj, vv.x, acc.x);
            acc.y = fmaf(pj, vv.y, acc.y);
        }

        if (i + NST < ntiles) issue(i % NST, i + NST);
    }

    // merge 8 warp-private (m, l, acc[64])
    float* rw = red + w * 66;
    if (lane == 0) { rw[0] = m_w; rw[1] = l_w; }
    *(float2*)(rw + 2 + lane * 2) = acc;
    __syncthreads();

    if (tid < HDIM) {
        float M = red[0];
#pragma unroll
        for (int k = 1; k < 8; k++) M = fmaxf(M, red[k * 66]);
        float L = 0.f, O = 0.f;
#pragma unroll
        for (int k = 0; k < 8; k++) {
            float c = exp2f(red[k * 66] - M);
            L = fmaf(red[k * 66 + 1], c, L);
            O = fmaf(red[k * 66 + 2 + tid], c, O);
        }
        float* po = part + (size_t)(bh * SPLIT + sp) * 68;
        po[2 + tid] = O;
        if (tid == 0) { po[0] = M; po[1] = L; }
    }
}

// ---------------------------------------------------------------------------
// Combine: 4 (b,h) groups per 256-thread block, SPLIT-unrolled loads.
// ---------------------------------------------------------------------------
__global__ void __launch_bounds__(256)
attn_combine(const float* __restrict__ qpart, const float* __restrict__ qbias,
             const float* __restrict__ part,
             const int* __restrict__ kvlen, float* __restrict__ oT)
{
    const int sub = threadIdx.x >> 6;
    const int d   = threadIdx.x & 63;
    const int bh  = blockIdx.x * 4 + sub;
    const int b   = bh >> 4;
    const int h   = bh & 15;
    const int len  = kvlen[b];
    const int nact = (len + SPLIT_ROWS - 1) / SPLIT_ROWS;

    float qd  = qkv_val(qpart, qbias, b, h * HDIM + d);
    float knd = qkv_val(qpart, qbias, b, DMODEL + h * HDIM + d);
    float vnd = qkv_val(qpart, qbias, b, 2 * DMODEL + h * HDIM + d);

    __shared__ float scr[4][64];
    __shared__ float snew_sh[4];
    scr[sub][d] = qd * knd;
    __syncthreads();
    if (d < 32) {
        float x = scr[sub][d] + scr[sub][d + 32];
#pragma unroll
        for (int off = 16; off > 0; off >>= 1)
            x += __shfl_xor_sync(0xffffffffu, x, off);
        if (d == 0) snew_sh[sub] = x * 0.125f * 1.4426950408889634f;
    }
    __syncthreads();

    float snew = snew_sh[sub];
    float ms[SPLIT], ls[SPLIT], Os[SPLIT];
    float M = snew;
#pragma unroll
    for (int s = 0; s < SPLIT; s++) {
        const float* po = part + (size_t)(bh * SPLIT + s) * 68;
        bool act = (s < nact);
        ms[s] = act ? po[0] : -1e30f;
        ls[s] = act ? po[1] : 0.f;
        Os[s] = act ? po[2 + d] : 0.f;
        M = fmaxf(M, ms[s]);
    }
    float pn = exp2f(snew - M);
    float L  = pn;
    float O  = pn * vnd;
#pragma unroll
    for (int s = 0; s < SPLIT; s++) {
        float c = exp2f(ms[s] - M);
        L = fmaf(ls[s], c, L);
        O = fmaf(Os[s], c, O);
    }
    oT[(size_t)(h * HDIM + d) * 64 + b] = O / L;
}

// ---------------------------------------------------------------------------
// Launch
// ---------------------------------------------------------------------------
extern "C" void kernel_launch(void* const* d_in, const int* in_sizes, int n_in,
                              void* d_out, int out_size)
{
    const float* x       = (const float*)d_in[0];
    const float* k_cache = (const float*)d_in[1];
    const float* v_cache = (const float*)d_in[2];
    const int*   kv_len  = (const int*)  d_in[4];
    const float* qkv_w   = (const float*)d_in[6];
    const float* qkv_b   = (const float*)d_in[7];
    const float* out_w   = (const float*)d_in[8];
    const float* out_b   = (const float*)d_in[9];
    const float* ln1_w   = (const float*)d_in[10];
    const float* ln1_b   = (const float*)d_in[11];
    const float* ln2_w   = (const float*)d_in[12];
    const float* ln2_b   = (const float*)d_in[13];
    const float* mlp_w1  = (const float*)d_in[14];
    const float* mlp_b1  = (const float*)d_in[15];
    const float* mlp_w2  = (const float*)d_in[16];
    const float* mlp_b2  = (const float*)d_in[17];
    float* out = (float*)d_out;

    float *p_xT, *p_oT, *p_ln1, *p_ln1T, *p_hT, *p_part, *p_pattn;
    cudaGetSymbolAddress((void**)&p_xT,    g_xT);
    cudaGetSymbolAddress((void**)&p_oT,    g_oT);
    cudaGetSymbolAddress((void**)&p_ln1,   g_ln1);
    cudaGetSymbolAddress((void**)&p_ln1T,  g_ln1T);
    cudaGetSymbolAddress((void**)&p_hT,    g_hT);
    cudaGetSymbolAddress((void**)&p_part,  g_part);
    cudaGetSymbolAddress((void**)&p_pattn, g_pattn);

    cudaFuncSetAttribute(attn4_kernel,
                         cudaFuncAttributeMaxDynamicSharedMemorySize, SMEM_BYTES);
    cudaFuncSetAttribute(gemmT_part,
                         cudaFuncAttributeMaxDynamicSharedMemorySize, G_SMEM_BYTES);

    // 1. transpose x -> xT [1024][64]
    transpose64<<<dim3(32, 2), dim3(32, 8)>>>(x, p_xT);

    // 2. QKV projection, split-K=2 -> part[0..1][64][3072]
    gemmT_part<<<dim3(96, 2), 128, G_SMEM_BYTES>>>(p_xT, qkv_w, p_part, 3072, 512);

    // 3. Attention decode, split-KV x4, warp-synchronous
    attn4_kernel<<<dim3(BATCH * NHEAD, SPLIT), 256, SMEM_BYTES>>>(
        p_part, qkv_b, k_cache, v_cache, kv_len, p_pattn);

    // 4. Combine partials + new token -> oT (4 heads per block)
    attn_combine<<<BATCH * NHEAD / 4, 256>>>(p_part, qkv_b, p_pattn, kv_len, p_oT);

    // 5. Output projection, split-K=4 -> part[0..3][64][1024]
    gemmT_part<<<dim3(32, 4), 128, G_SMEM_BYTES>>>(p_oT, out_w, p_part, 1024, 256);

    // 6. reduce + bias + residual(x) + LN1 -> ln1 (+ ln1T)
    reduce_ln<4, true><<<BATCH, 256>>>(p_part, out_b, x, ln1_w, ln1_b,
                                       p_ln1, p_ln1T);

    // 7. MLP up, split-K=2 -> part[0..1][64][4096]
    gemmT_part<<<dim3(128, 2), 128, G_SMEM_BYTES>>>(p_ln1T, mlp_w1, p_part, 4096, 512);

    // 8. hT = relu(part0 + part1 + bias), transposed
    relu_reduce_t<<<dim3(128, 2), dim3(32, 8)>>>(p_part, mlp_b1, p_hT);

    // 9. MLP down, split-K=8 -> part[0..7][64][1024]
    gemmT_part<<<dim3(32, 8), 128, G_SMEM_BYTES>>>(p_hT, mlp_w2, p_part, 1024, 512);

    // 10. reduce + bias + residual(ln1) + LN2 -> out
    reduce_ln<8, false><<<BATCH, 256>>>(p_part, mlp_b2, p_ln1, ln2_w, ln2_b,
                                        out, nullptr);
}